// round 4
// baseline (speedup 1.0000x reference)
#include <cuda_runtime.h>
#include <math.h>

#define N_B   8
#define N_SEQ 1024
#define DM    1024
#define NH    16
#define HD    64

// Scratch (allocation-free: device globals)
__device__ float g_qkv[(size_t)N_B * N_SEQ * 3 * DM];      // 100.7 MB
__device__ float g_q[(size_t)N_B * NH * N_SEQ * HD];       // 33.5 MB
__device__ float g_k[(size_t)N_B * NH * N_SEQ * HD];
__device__ float g_v[(size_t)N_B * NH * N_SEQ * HD];
__device__ float g_o[(size_t)N_B * N_SEQ * DM];            // attention output [b,n,h*d]

// ---------------------------------------------------------------------------
// SGEMM: C[M,N] = A[M,K] @ B[K,N] + bias[N]
// 128x128 block tile, BK=8, 256 threads, 8x8 per-thread microtile.
// M % 128 == 0, N % 128 == 0, K % 8 == 0 guaranteed by problem shapes.
// ---------------------------------------------------------------------------
__global__ __launch_bounds__(256)
void sgemm_bias(const float* __restrict__ A, const float* __restrict__ B,
                const float* __restrict__ bias, float* __restrict__ C,
                int M, int N, int K)
{
    constexpr int BM = 128, BN = 128, BK = 8, TM = 8, TN = 8;
    __shared__ float As[BK][BM];
    __shared__ float Bs[BK][BN];

    const int tid = threadIdx.x;
    const int tx = tid % (BN / TN);  // 0..15
    const int ty = tid / (BN / TN);  // 0..15
    const int row0 = blockIdx.y * BM;
    const int col0 = blockIdx.x * BN;

    // A: 128 rows x 8 cols = 256 float4 loads (one per thread)
    const int a_row  = tid >> 1;           // 0..127
    const int a_col4 = (tid & 1) * 4;      // 0 or 4
    // B: 8 rows x 128 cols = 256 float4 loads
    const int b_row  = tid >> 5;           // 0..7
    const int b_col4 = (tid & 31) * 4;     // 0..124

    const float* Aptr = A + (size_t)(row0 + a_row) * K + a_col4;
    const float* Bptr = B + (size_t)b_row * N + col0 + b_col4;

    float acc[TM][TN] = {};

    for (int k0 = 0; k0 < K; k0 += BK) {
        float4 av = *(const float4*)(Aptr + k0);
        As[a_col4 + 0][a_row] = av.x;
        As[a_col4 + 1][a_row] = av.y;
        As[a_col4 + 2][a_row] = av.z;
        As[a_col4 + 3][a_row] = av.w;
        float4 bv = *(const float4*)(Bptr + (size_t)k0 * N);
        *(float4*)&Bs[b_row][b_col4] = bv;
        __syncthreads();

        #pragma unroll
        for (int kk = 0; kk < BK; kk++) {
            float a[TM], b[TN];
            #pragma unroll
            for (int i = 0; i < TM; i++) a[i] = As[kk][ty * TM + i];
            #pragma unroll
            for (int j = 0; j < TN; j++) b[j] = Bs[kk][tx * TN + j];
            #pragma unroll
            for (int i = 0; i < TM; i++)
                #pragma unroll
                for (int j = 0; j < TN; j++)
                    acc[i][j] += a[i] * b[j];
        }
        __syncthreads();
    }

    #pragma unroll
    for (int i = 0; i < TM; i++) {
        const int r = row0 + ty * TM + i;
        #pragma unroll
        for (int j = 0; j < TN; j += 4) {
            const int c = col0 + tx * TN + j;
            float4 o;
            o.x = acc[i][j + 0] + bias[c + 0];
            o.y = acc[i][j + 1] + bias[c + 1];
            o.z = acc[i][j + 2] + bias[c + 2];
            o.w = acc[i][j + 3] + bias[c + 3];
            *(float4*)&C[(size_t)r * N + c] = o;
        }
    }
}

// ---------------------------------------------------------------------------
// Prep: qkv[b,n,3,h,d] -> RMSNorm(q,k) -> image RoPE(q,k) -> L2-norm(q,k)
// -> write q,k,v in [b,h,n,d] layout.
// One warp per (b,n,h). Lane l owns dims l and l+32 (rotate-half pair).
// ---------------------------------------------------------------------------
__global__ __launch_bounds__(256)
void prep_kernel(const float* __restrict__ qkv,
                 const float* __restrict__ q_gain,
                 const float* __restrict__ k_gain)
{
    const int w = (blockIdx.x * blockDim.x + threadIdx.x) >> 5;
    const int lane = threadIdx.x & 31;
    if (w >= N_B * N_SEQ * NH) return;
    const int h  = w % NH;
    const int bn = w / NH;          // b*N_SEQ + n
    const int n  = bn % N_SEQ;
    const int b  = bn / N_SEQ;

    const float* base = qkv + (size_t)bn * (3 * DM) + h * HD;
    float q0 = base[lane],          q1 = base[lane + 32];
    float k0 = base[DM + lane],     k1 = base[DM + lane + 32];
    float v0 = base[2 * DM + lane], v1 = base[2 * DM + lane + 32];

    // 2D axial RoPE angle for dim pair (lane, lane+32). side = 32.
    const float pos = (lane < 16) ? (float)(n >> 5) : (float)(n & 31);
    // freqs[f] = 10000^(-f/16), f = lane % 16
    const float fr = expf(-((float)(lane & 15) * (1.0f / 16.0f)) * 9.210340371976184f);
    float s, c;
    sincosf(pos * fr, &s, &c);

    const float gq0 = q_gain[lane], gq1 = q_gain[lane + 32];
    const float gk0 = k_gain[lane], gk1 = k_gain[lane + 32];

    // ---- Q ----
    float ssq = q0 * q0 + q1 * q1;
    #pragma unroll
    for (int o = 16; o; o >>= 1) ssq += __shfl_xor_sync(0xffffffffu, ssq, o);
    float r = rsqrtf(ssq * (1.0f / 64.0f) + 1e-6f);
    q0 *= r * gq0;  q1 *= r * gq1;
    float t0 = q0 * c - q1 * s;
    float t1 = q1 * c + q0 * s;
    float l2 = t0 * t0 + t1 * t1;
    #pragma unroll
    for (int o = 16; o; o >>= 1) l2 += __shfl_xor_sync(0xffffffffu, l2, o);
    float inv = rsqrtf(l2);
    t0 *= inv;  t1 *= inv;

    const size_t obase = (((size_t)(b * NH + h)) * N_SEQ + n) * HD;
    g_q[obase + lane] = t0;  g_q[obase + lane + 32] = t1;

    // ---- K ----
    ssq = k0 * k0 + k1 * k1;
    #pragma unroll
    for (int o = 16; o; o >>= 1) ssq += __shfl_xor_sync(0xffffffffu, ssq, o);
    r = rsqrtf(ssq * (1.0f / 64.0f) + 1e-6f);
    k0 *= r * gk0;  k1 *= r * gk1;
    t0 = k0 * c - k1 * s;
    t1 = k1 * c + k0 * s;
    l2 = t0 * t0 + t1 * t1;
    #pragma unroll
    for (int o = 16; o; o >>= 1) l2 += __shfl_xor_sync(0xffffffffu, l2, o);
    inv = rsqrtf(l2);
    t0 *= inv;  t1 *= inv;
    g_k[obase + lane] = t0;  g_k[obase + lane + 32] = t1;

    // ---- V (pure layout transform) ----
    g_v[obase + lane] = v0;  g_v[obase + lane + 32] = v1;
}

// ---------------------------------------------------------------------------
// Flash-style cosine-sim attention (scale=8), fp32.
// Block: 256 threads = 128 queries x 2 d-halves. K/V tiles of 64 in smem.
// Output written in [b, n, h, d] layout into g_o (ready for out-proj GEMM).
// ---------------------------------------------------------------------------
__global__ __launch_bounds__(256)
void attn_kernel(float* __restrict__ outp)
{
    __shared__ float ksh[64][64];
    __shared__ float vsh[64][64];

    const int h = blockIdx.y, b = blockIdx.z;
    const int t = threadIdx.x;
    const int qi = blockIdx.x * 128 + (t >> 1);
    const int cb = (t & 1) * 32;

    const size_t bh = ((size_t)b * NH + h) * N_SEQ * HD;

    float qr[32];
    {
        const float* qp = g_q + bh + (size_t)qi * HD + cb;
        #pragma unroll
        for (int i = 0; i < 32; i += 4) {
            float4 v4 = *(const float4*)(qp + i);
            qr[i] = v4.x; qr[i + 1] = v4.y; qr[i + 2] = v4.z; qr[i + 3] = v4.w;
        }
    }

    float oacc[32] = {};
    float m = -1e30f, l = 0.0f;

    for (int kt = 0; kt < N_SEQ / 64; kt++) {
        const float4* kp = (const float4*)(g_k + bh + (size_t)kt * 64 * HD);
        const float4* vp = (const float4*)(g_v + bh + (size_t)kt * 64 * HD);
        #pragma unroll
        for (int i = 0; i < 4; i++) {
            const int idx = t + i * 256;     // 1024 float4 per tile
            ((float4*)ksh)[idx] = kp[idx];
            ((float4*)vsh)[idx] = vp[idx];
        }
        __syncthreads();

        for (int j = 0; j < 64; j++) {
            const float4* kr = (const float4*)&ksh[j][cb];
            float p0 = 0.f, p1 = 0.f, p2 = 0.f, p3 = 0.f;
            #pragma unroll
            for (int i = 0; i < 8; i += 4) {
                float4 k4a = kr[i],     k4b = kr[i + 1];
                float4 k4c = kr[i + 2], k4d = kr[i + 3];
                p0 += k4a.x * qr[4*i+0]  + k4a.y * qr[4*i+1]  + k4a.z * qr[4*i+2]  + k4a.w * qr[4*i+3];
                p1 += k4b.x * qr[4*i+4]  + k4b.y * qr[4*i+5]  + k4b.z * qr[4*i+6]  + k4b.w * qr[4*i+7];
                p2 += k4c.x * qr[4*i+8]  + k4c.y * qr[4*i+9]  + k4c.z * qr[4*i+10] + k4c.w * qr[4*i+11];
                p3 += k4d.x * qr[4*i+12] + k4d.y * qr[4*i+13] + k4d.z * qr[4*i+14] + k4d.w * qr[4*i+15];
            }
            float part = (p0 + p1) + (p2 + p3);
            float sc = (part + __shfl_xor_sync(0xffffffffu, part, 1)) * 8.0f;

            if (sc > m) {
                const float f = __expf(m - sc);
                m = sc;
                l *= f;
                #pragma unroll
                for (int i = 0; i < 32; i++) oacc[i] *= f;
            }
            const float p = __expf(sc - m);
            l += p;
            const float4* vr = (const float4*)&vsh[j][cb];
            #pragma unroll
            for (int i = 0; i < 8; i++) {
                float4 v4 = vr[i];
                oacc[4*i+0] += p * v4.x;
                oacc[4*i+1] += p * v4.y;
                oacc[4*i+2] += p * v4.z;
                oacc[4*i+3] += p * v4.w;
            }
        }
        __syncthreads();
    }

    const float inv = 1.0f / l;
    float* op = outp + (((size_t)b * N_SEQ + qi) * NH + h) * HD + cb;
    #pragma unroll
    for (int i = 0; i < 32; i += 4) {
        float4 v4;
        v4.x = oacc[i] * inv;  v4.y = oacc[i + 1] * inv;
        v4.z = oacc[i + 2] * inv;  v4.w = oacc[i + 3] * inv;
        *(float4*)(op + i) = v4;
    }
}

// ---------------------------------------------------------------------------
extern "C" void kernel_launch(void* const* d_in, const int* in_sizes, int n_in,
                              void* d_out, int out_size)
{
    const float* x      = (const float*)d_in[0];
    const float* w_qkv  = (const float*)d_in[1];
    const float* b_qkv  = (const float*)d_in[2];
    const float* q_gain = (const float*)d_in[3];
    const float* k_gain = (const float*)d_in[4];
    const float* w_out  = (const float*)d_in[5];
    const float* b_out  = (const float*)d_in[6];
    float* out = (float*)d_out;

    float *qkv_p, *o_p;
    cudaGetSymbolAddress((void**)&qkv_p, g_qkv);
    cudaGetSymbolAddress((void**)&o_p, g_o);

    const int M = N_B * N_SEQ;  // 8192

    // 1) QKV projection: [8192,1024] @ [1024,3072] + b_qkv
    sgemm_bias<<<dim3((3 * DM) / 128, M / 128), 256>>>(x, w_qkv, b_qkv, qkv_p, M, 3 * DM, DM);

    // 2) RMSNorm + RoPE + L2-norm + head transpose
    prep_kernel<<<(N_B * N_SEQ * NH * 32) / 256, 256>>>(qkv_p, q_gain, k_gain);

    // 3) Cosine-sim attention
    attn_kernel<<<dim3(N_SEQ / 128, NH, N_B), 256>>>(o_p);

    // 4) Output projection: [8192,1024] @ [1024,1024] + b_out
    sgemm_bias<<<dim3(DM / 128, M / 128), 256>>>(o_p, w_out, b_out, out, M, DM, DM);
}

// round 8
// speedup vs baseline: 1.3514x; 1.3514x over previous
#include <cuda_runtime.h>
#include <math.h>
#include <stdint.h>

#define N_B   8
#define N_SEQ 1024
#define DM    1024
#define NH    16
#define HD    64

// Scratch (allocation-free: device globals)
__device__ float g_qkv[(size_t)N_B * N_SEQ * 3 * DM];
__device__ float g_q[(size_t)N_B * NH * N_SEQ * HD];
__device__ float g_k[(size_t)N_B * NH * N_SEQ * HD];
__device__ float g_v[(size_t)N_B * NH * N_SEQ * HD];
__device__ float g_o[(size_t)N_B * N_SEQ * DM];

// ---------------------------------------------------------------------------
// TF32 tensor-core GEMM: C[M,N] = A[M,K] @ B[K,N] + bias[N]
// 128x128 block tile, BK=16, 256 threads = 8 warps (4x2), warp tile 32x64,
// mma.sync.m16n8k8 tf32, fp32 accumulate. Register prefetch, single smem buf.
// ---------------------------------------------------------------------------
__device__ __forceinline__ uint32_t f2tf32(float x) {
    uint32_t r;
    asm("cvt.rna.tf32.f32 %0, %1;" : "=r"(r) : "f"(x));
    return r;
}

__device__ __forceinline__ void mma_tf32(float c[4],
                                         uint32_t a0, uint32_t a1, uint32_t a2, uint32_t a3,
                                         uint32_t b0, uint32_t b1) {
    asm volatile(
        "mma.sync.aligned.m16n8k8.row.col.f32.tf32.tf32.f32 "
        "{%0,%1,%2,%3}, {%4,%5,%6,%7}, {%8,%9}, {%0,%1,%2,%3};\n"
        : "+f"(c[0]), "+f"(c[1]), "+f"(c[2]), "+f"(c[3])
        : "r"(a0), "r"(a1), "r"(a2), "r"(a3), "r"(b0), "r"(b1));
}

__global__ __launch_bounds__(256)
void sgemm_tf32(const float* __restrict__ A, const float* __restrict__ B,
                const float* __restrict__ bias, float* __restrict__ C,
                int M, int N, int K)
{
    constexpr int BM = 128, BN = 128, BK = 16;
    constexpr int LDA = 136;   // padded: stride % 32 == 8 -> conflict-free frag reads
    __shared__ uint32_t As[BK][LDA];   // As[k][m]  (tf32 bits)
    __shared__ uint32_t Bs[BK][LDA];   // Bs[k][n]

    const int tid  = threadIdx.x;
    const int lane = tid & 31;
    const int warp = tid >> 5;
    const int warpM = warp & 3;        // 0..3 -> 32-row slice
    const int warpN = warp >> 2;       // 0..1 -> 64-col slice
    const int lm = lane >> 2;          // 0..7
    const int lk = lane & 3;           // 0..3

    const int row0 = blockIdx.y * BM;
    const int col0 = blockIdx.x * BN;

    // Global-load mapping: A tile 128x16 (8 floats/thread), B tile 16x128
    const int a_row = tid >> 1;            // 0..127
    const int a_col = (tid & 1) * 8;       // 0 or 8
    const int b_row = tid >> 4;            // 0..15
    const int b_col = (tid & 15) * 8;      // 0..120

    const float* Aptr = A + (size_t)(row0 + a_row) * K + a_col;
    const float* Bptr = B + (size_t)b_row * N + col0 + b_col;

    float acc[2][8][4] = {};

    // Prologue: tile 0 -> smem
    {
        float4 a0 = *(const float4*)(Aptr);
        float4 a1 = *(const float4*)(Aptr + 4);
        float4 b0 = *(const float4*)(Bptr);
        float4 b1 = *(const float4*)(Bptr + 4);
        As[a_col + 0][a_row] = f2tf32(a0.x); As[a_col + 1][a_row] = f2tf32(a0.y);
        As[a_col + 2][a_row] = f2tf32(a0.z); As[a_col + 3][a_row] = f2tf32(a0.w);
        As[a_col + 4][a_row] = f2tf32(a1.x); As[a_col + 5][a_row] = f2tf32(a1.y);
        As[a_col + 6][a_row] = f2tf32(a1.z); As[a_col + 7][a_row] = f2tf32(a1.w);
        uint4 u0 = { f2tf32(b0.x), f2tf32(b0.y), f2tf32(b0.z), f2tf32(b0.w) };
        uint4 u1 = { f2tf32(b1.x), f2tf32(b1.y), f2tf32(b1.z), f2tf32(b1.w) };
        *(uint4*)&Bs[b_row][b_col]     = u0;
        *(uint4*)&Bs[b_row][b_col + 4] = u1;
    }
    __syncthreads();

    for (int k0 = 0; k0 < K; k0 += BK) {
        const bool last = (k0 + BK >= K);
        float4 na0, na1, nb0, nb1;
        if (!last) {
            na0 = *(const float4*)(Aptr + k0 + BK);
            na1 = *(const float4*)(Aptr + k0 + BK + 4);
            nb0 = *(const float4*)(Bptr + (size_t)(k0 + BK) * N);
            nb1 = *(const float4*)(Bptr + (size_t)(k0 + BK) * N + 4);
        }

        #pragma unroll
        for (int ks = 0; ks < 2; ks++) {
            uint32_t af[2][4];
            #pragma unroll
            for (int mm = 0; mm < 2; mm++) {
                const int mb = warpM * 32 + mm * 16 + lm;
                af[mm][0] = As[ks * 8 + lk][mb];
                af[mm][1] = As[ks * 8 + lk][mb + 8];
                af[mm][2] = As[ks * 8 + lk + 4][mb];
                af[mm][3] = As[ks * 8 + lk + 4][mb + 8];
            }
            uint32_t bf[8][2];
            #pragma unroll
            for (int nn = 0; nn < 8; nn++) {
                const int nb = warpN * 64 + nn * 8 + lm;
                bf[nn][0] = Bs[ks * 8 + lk][nb];
                bf[nn][1] = Bs[ks * 8 + lk + 4][nb];
            }
            #pragma unroll
            for (int mm = 0; mm < 2; mm++)
                #pragma unroll
                for (int nn = 0; nn < 8; nn++)
                    mma_tf32(acc[mm][nn], af[mm][0], af[mm][1], af[mm][2], af[mm][3],
                             bf[nn][0], bf[nn][1]);
        }
        __syncthreads();

        if (!last) {
            As[a_col + 0][a_row] = f2tf32(na0.x); As[a_col + 1][a_row] = f2tf32(na0.y);
            As[a_col + 2][a_row] = f2tf32(na0.z); As[a_col + 3][a_row] = f2tf32(na0.w);
            As[a_col + 4][a_row] = f2tf32(na1.x); As[a_col + 5][a_row] = f2tf32(na1.y);
            As[a_col + 6][a_row] = f2tf32(na1.z); As[a_col + 7][a_row] = f2tf32(na1.w);
            uint4 u0 = { f2tf32(nb0.x), f2tf32(nb0.y), f2tf32(nb0.z), f2tf32(nb0.w) };
            uint4 u1 = { f2tf32(nb1.x), f2tf32(nb1.y), f2tf32(nb1.z), f2tf32(nb1.w) };
            *(uint4*)&Bs[b_row][b_col]     = u0;
            *(uint4*)&Bs[b_row][b_col + 4] = u1;
            __syncthreads();
        }
    }

    // Epilogue: c0,c1 at (row = lane/4, col = 2*(lane%4)); c2,c3 at row+8
    #pragma unroll
    for (int mm = 0; mm < 2; mm++) {
        #pragma unroll
        for (int nn = 0; nn < 8; nn++) {
            const int r = row0 + warpM * 32 + mm * 16 + lm;
            const int c = col0 + warpN * 64 + nn * 8 + 2 * lk;
            float2 o0 = { acc[mm][nn][0] + bias[c], acc[mm][nn][1] + bias[c + 1] };
            float2 o1 = { acc[mm][nn][2] + bias[c], acc[mm][nn][3] + bias[c + 1] };
            *(float2*)&C[(size_t)r * N + c]       = o0;
            *(float2*)&C[(size_t)(r + 8) * N + c] = o1;
        }
    }
}

// ---------------------------------------------------------------------------
// Prep: qkv[b,n,3,h,d] -> RMSNorm(q,k) -> image RoPE(q,k) -> L2-norm(q,k)
// -> write q,k,v in [b,h,n,d] layout. One warp per (b,n,h).
// ---------------------------------------------------------------------------
__global__ __launch_bounds__(256)
void prep_kernel(const float* __restrict__ qkv,
                 const float* __restrict__ q_gain,
                 const float* __restrict__ k_gain)
{
    const int w = (blockIdx.x * blockDim.x + threadIdx.x) >> 5;
    const int lane = threadIdx.x & 31;
    if (w >= N_B * N_SEQ * NH) return;
    const int h  = w % NH;
    const int bn = w / NH;
    const int n  = bn % N_SEQ;
    const int b  = bn / N_SEQ;

    const float* base = qkv + (size_t)bn * (3 * DM) + h * HD;
    float q0 = base[lane],          q1 = base[lane + 32];
    float k0 = base[DM + lane],     k1 = base[DM + lane + 32];
    float v0 = base[2 * DM + lane], v1 = base[2 * DM + lane + 32];

    const float pos = (lane < 16) ? (float)(n >> 5) : (float)(n & 31);
    const float fr = expf(-((float)(lane & 15) * (1.0f / 16.0f)) * 9.210340371976184f);
    float s, c;
    sincosf(pos * fr, &s, &c);

    const float gq0 = q_gain[lane], gq1 = q_gain[lane + 32];
    const float gk0 = k_gain[lane], gk1 = k_gain[lane + 32];

    // ---- Q ----
    float ssq = q0 * q0 + q1 * q1;
    #pragma unroll
    for (int o = 16; o; o >>= 1) ssq += __shfl_xor_sync(0xffffffffu, ssq, o);
    float r = rsqrtf(ssq * (1.0f / 64.0f) + 1e-6f);
    q0 *= r * gq0;  q1 *= r * gq1;
    float t0 = q0 * c - q1 * s;
    float t1 = q1 * c + q0 * s;
    float l2 = t0 * t0 + t1 * t1;
    #pragma unroll
    for (int o = 16; o; o >>= 1) l2 += __shfl_xor_sync(0xffffffffu, l2, o);
    float inv = rsqrtf(l2);
    t0 *= inv;  t1 *= inv;

    const size_t obase = (((size_t)(b * NH + h)) * N_SEQ + n) * HD;
    g_q[obase + lane] = t0;  g_q[obase + lane + 32] = t1;

    // ---- K ----
    ssq = k0 * k0 + k1 * k1;
    #pragma unroll
    for (int o = 16; o; o >>= 1) ssq += __shfl_xor_sync(0xffffffffu, ssq, o);
    r = rsqrtf(ssq * (1.0f / 64.0f) + 1e-6f);
    k0 *= r * gk0;  k1 *= r * gk1;
    t0 = k0 * c - k1 * s;
    t1 = k1 * c + k0 * s;
    l2 = t0 * t0 + t1 * t1;
    #pragma unroll
    for (int o = 16; o; o >>= 1) l2 += __shfl_xor_sync(0xffffffffu, l2, o);
    inv = rsqrtf(l2);
    t0 *= inv;  t1 *= inv;
    g_k[obase + lane] = t0;  g_k[obase + lane + 32] = t1;

    g_v[obase + lane] = v0;  g_v[obase + lane + 32] = v1;
}

// ---------------------------------------------------------------------------
// Cosine-sim attention, fp32. Scores are bounded: |q|=|k|=1 => score <= 8.
// Fixed softmax max = 8: p = exp(8*s - 8), no online max / rescale needed.
// Block: 256 threads = 128 queries x 2 d-halves. K/V tiles of 64 in smem.
// ---------------------------------------------------------------------------
__global__ __launch_bounds__(256)
void attn_kernel(float* __restrict__ outp)
{
    __shared__ float ksh[64][64];
    __shared__ float vsh[64][64];

    const int h = blockIdx.y, b = blockIdx.z;
    const int t = threadIdx.x;
    const int qi = blockIdx.x * 128 + (t >> 1);
    const int cb = (t & 1) * 32;

    const size_t bh = ((size_t)b * NH + h) * N_SEQ * HD;

    float qr[32];
    {
        const float* qp = g_q + bh + (size_t)qi * HD + cb;
        #pragma unroll
        for (int i = 0; i < 32; i += 4) {
            float4 v4 = *(const float4*)(qp + i);
            qr[i] = v4.x; qr[i + 1] = v4.y; qr[i + 2] = v4.z; qr[i + 3] = v4.w;
        }
    }

    float oacc[32] = {};
    float l = 0.0f;

    for (int kt = 0; kt < N_SEQ / 64; kt++) {
        const float4* kp = (const float4*)(g_k + bh + (size_t)kt * 64 * HD);
        const float4* vp = (const float4*)(g_v + bh + (size_t)kt * 64 * HD);
        #pragma unroll
        for (int i = 0; i < 4; i++) {
            const int idx = t + i * 256;
            ((float4*)ksh)[idx] = kp[idx];
            ((float4*)vsh)[idx] = vp[idx];
        }
        __syncthreads();

        #pragma unroll 2
        for (int j = 0; j < 64; j += 2) {
            const float4* kr0 = (const float4*)&ksh[j][cb];
            const float4* kr1 = (const float4*)&ksh[j + 1][cb];
            float s0 = 0.f, s1 = 0.f;
            #pragma unroll
            for (int i = 0; i < 8; i++) {
                float4 ka = kr0[i];
                float4 kb = kr1[i];
                s0 += ka.x * qr[4*i] + ka.y * qr[4*i+1] + ka.z * qr[4*i+2] + ka.w * qr[4*i+3];
                s1 += kb.x * qr[4*i] + kb.y * qr[4*i+1] + kb.z * qr[4*i+2] + kb.w * qr[4*i+3];
            }
            const float f0 = s0 + __shfl_xor_sync(0xffffffffu, s0, 1);
            const float f1 = s1 + __shfl_xor_sync(0xffffffffu, s1, 1);
            const float p0 = __expf(8.0f * f0 - 8.0f);   // score <= 8 always
            const float p1 = __expf(8.0f * f1 - 8.0f);
            l += p0 + p1;
            const float4* vr0 = (const float4*)&vsh[j][cb];
            const float4* vr1 = (const float4*)&vsh[j + 1][cb];
            #pragma unroll
            for (int i = 0; i < 8; i++) {
                float4 va = vr0[i];
                float4 vb = vr1[i];
                oacc[4*i+0] += p0 * va.x + p1 * vb.x;
                oacc[4*i+1] += p0 * va.y + p1 * vb.y;
                oacc[4*i+2] += p0 * va.z + p1 * vb.z;
                oacc[4*i+3] += p0 * va.w + p1 * vb.w;
            }
        }
        __syncthreads();
    }

    const float inv = 1.0f / l;
    float* op = outp + (((size_t)b * N_SEQ + qi) * NH + h) * HD + cb;
    #pragma unroll
    for (int i = 0; i < 32; i += 4) {
        float4 v4;
        v4.x = oacc[i] * inv;  v4.y = oacc[i + 1] * inv;
        v4.z = oacc[i + 2] * inv;  v4.w = oacc[i + 3] * inv;
        *(float4*)(op + i) = v4;
    }
}

// ---------------------------------------------------------------------------
extern "C" void kernel_launch(void* const* d_in, const int* in_sizes, int n_in,
                              void* d_out, int out_size)
{
    const float* x      = (const float*)d_in[0];
    const float* w_qkv  = (const float*)d_in[1];
    const float* b_qkv  = (const float*)d_in[2];
    const float* q_gain = (const float*)d_in[3];
    const float* k_gain = (const float*)d_in[4];
    const float* w_out  = (const float*)d_in[5];
    const float* b_out  = (const float*)d_in[6];
    float* out = (float*)d_out;

    float *qkv_p, *o_p;
    cudaGetSymbolAddress((void**)&qkv_p, g_qkv);
    cudaGetSymbolAddress((void**)&o_p, g_o);

    const int M = N_B * N_SEQ;  // 8192

    // 1) QKV projection (tf32 tensor cores)
    sgemm_tf32<<<dim3((3 * DM) / 128, M / 128), 256>>>(x, w_qkv, b_qkv, qkv_p, M, 3 * DM, DM);

    // 2) RMSNorm + RoPE + L2-norm + head transpose
    prep_kernel<<<(N_B * N_SEQ * NH * 32) / 256, 256>>>(qkv_p, q_gain, k_gain);

    // 3) Cosine-sim attention (fixed-max softmax)
    attn_kernel<<<dim3(N_SEQ / 128, NH, N_B), 256>>>(o_p);

    // 4) Output projection (tf32 tensor cores)
    sgemm_tf32<<<dim3(DM / 128, M / 128), 256>>>(o_p, w_out, b_out, out, M, DM, DM);
}

// round 9
// speedup vs baseline: 2.7852x; 2.0609x over previous
#include <cuda_runtime.h>
#include <math.h>
#include <stdint.h>

#define N_B   8
#define N_SEQ 1024
#define DM    1024
#define NH    16
#define HD    64

// Scratch (allocation-free: device globals)
__device__ float g_qkv[(size_t)N_B * N_SEQ * 3 * DM];
__device__ float g_q[(size_t)N_B * NH * N_SEQ * HD];
__device__ float g_k[(size_t)N_B * NH * N_SEQ * HD];
__device__ float g_v[(size_t)N_B * NH * N_SEQ * HD];
__device__ float g_o[(size_t)N_B * N_SEQ * DM];

// ---------------------------------------------------------------------------
// tf32 helpers
// ---------------------------------------------------------------------------
__device__ __forceinline__ uint32_t f2tf32(float x) {
    uint32_t r;
    asm("cvt.rna.tf32.f32 %0, %1;" : "=r"(r) : "f"(x));
    return r;
}
__device__ __forceinline__ void tf32_split(float x, uint32_t& hi, uint32_t& lo) {
    hi = f2tf32(x);
    lo = f2tf32(x - __uint_as_float(hi));
}
__device__ __forceinline__ void mma_tf32(float c[4],
                                         uint32_t a0, uint32_t a1, uint32_t a2, uint32_t a3,
                                         uint32_t b0, uint32_t b1) {
    asm volatile(
        "mma.sync.aligned.m16n8k8.row.col.f32.tf32.tf32.f32 "
        "{%0,%1,%2,%3}, {%4,%5,%6,%7}, {%8,%9}, {%0,%1,%2,%3};\n"
        : "+f"(c[0]), "+f"(c[1]), "+f"(c[2]), "+f"(c[3])
        : "r"(a0), "r"(a1), "r"(a2), "r"(a3), "r"(b0), "r"(b1));
}

// ---------------------------------------------------------------------------
// TF32 tensor-core GEMM: C = A@B + bias (unchanged from R4, known-good)
// ---------------------------------------------------------------------------
__global__ __launch_bounds__(256)
void sgemm_tf32(const float* __restrict__ A, const float* __restrict__ B,
                const float* __restrict__ bias, float* __restrict__ C,
                int M, int N, int K)
{
    constexpr int BM = 128, BN = 128, BK = 16;
    constexpr int LDA = 136;
    __shared__ uint32_t As[BK][LDA];
    __shared__ uint32_t Bs[BK][LDA];

    const int tid  = threadIdx.x;
    const int lane = tid & 31;
    const int warp = tid >> 5;
    const int warpM = warp & 3;
    const int warpN = warp >> 2;
    const int lm = lane >> 2;
    const int lk = lane & 3;

    const int row0 = blockIdx.y * BM;
    const int col0 = blockIdx.x * BN;

    const int a_row = tid >> 1;
    const int a_col = (tid & 1) * 8;
    const int b_row = tid >> 4;
    const int b_col = (tid & 15) * 8;

    const float* Aptr = A + (size_t)(row0 + a_row) * K + a_col;
    const float* Bptr = B + (size_t)b_row * N + col0 + b_col;

    float acc[2][8][4] = {};

    {
        float4 a0 = *(const float4*)(Aptr);
        float4 a1 = *(const float4*)(Aptr + 4);
        float4 b0 = *(const float4*)(Bptr);
        float4 b1 = *(const float4*)(Bptr + 4);
        As[a_col + 0][a_row] = f2tf32(a0.x); As[a_col + 1][a_row] = f2tf32(a0.y);
        As[a_col + 2][a_row] = f2tf32(a0.z); As[a_col + 3][a_row] = f2tf32(a0.w);
        As[a_col + 4][a_row] = f2tf32(a1.x); As[a_col + 5][a_row] = f2tf32(a1.y);
        As[a_col + 6][a_row] = f2tf32(a1.z); As[a_col + 7][a_row] = f2tf32(a1.w);
        uint4 u0 = { f2tf32(b0.x), f2tf32(b0.y), f2tf32(b0.z), f2tf32(b0.w) };
        uint4 u1 = { f2tf32(b1.x), f2tf32(b1.y), f2tf32(b1.z), f2tf32(b1.w) };
        *(uint4*)&Bs[b_row][b_col]     = u0;
        *(uint4*)&Bs[b_row][b_col + 4] = u1;
    }
    __syncthreads();

    for (int k0 = 0; k0 < K; k0 += BK) {
        const bool last = (k0 + BK >= K);
        float4 na0, na1, nb0, nb1;
        if (!last) {
            na0 = *(const float4*)(Aptr + k0 + BK);
            na1 = *(const float4*)(Aptr + k0 + BK + 4);
            nb0 = *(const float4*)(Bptr + (size_t)(k0 + BK) * N);
            nb1 = *(const float4*)(Bptr + (size_t)(k0 + BK) * N + 4);
        }

        #pragma unroll
        for (int ks = 0; ks < 2; ks++) {
            uint32_t af[2][4];
            #pragma unroll
            for (int mm = 0; mm < 2; mm++) {
                const int mb = warpM * 32 + mm * 16 + lm;
                af[mm][0] = As[ks * 8 + lk][mb];
                af[mm][1] = As[ks * 8 + lk][mb + 8];
                af[mm][2] = As[ks * 8 + lk + 4][mb];
                af[mm][3] = As[ks * 8 + lk + 4][mb + 8];
            }
            uint32_t bf[8][2];
            #pragma unroll
            for (int nn = 0; nn < 8; nn++) {
                const int nb = warpN * 64 + nn * 8 + lm;
                bf[nn][0] = Bs[ks * 8 + lk][nb];
                bf[nn][1] = Bs[ks * 8 + lk + 4][nb];
            }
            #pragma unroll
            for (int mm = 0; mm < 2; mm++)
                #pragma unroll
                for (int nn = 0; nn < 8; nn++)
                    mma_tf32(acc[mm][nn], af[mm][0], af[mm][1], af[mm][2], af[mm][3],
                             bf[nn][0], bf[nn][1]);
        }
        __syncthreads();

        if (!last) {
            As[a_col + 0][a_row] = f2tf32(na0.x); As[a_col + 1][a_row] = f2tf32(na0.y);
            As[a_col + 2][a_row] = f2tf32(na0.z); As[a_col + 3][a_row] = f2tf32(na0.w);
            As[a_col + 4][a_row] = f2tf32(na1.x); As[a_col + 5][a_row] = f2tf32(na1.y);
            As[a_col + 6][a_row] = f2tf32(na1.z); As[a_col + 7][a_row] = f2tf32(na1.w);
            uint4 u0 = { f2tf32(nb0.x), f2tf32(nb0.y), f2tf32(nb0.z), f2tf32(nb0.w) };
            uint4 u1 = { f2tf32(nb1.x), f2tf32(nb1.y), f2tf32(nb1.z), f2tf32(nb1.w) };
            *(uint4*)&Bs[b_row][b_col]     = u0;
            *(uint4*)&Bs[b_row][b_col + 4] = u1;
            __syncthreads();
        }
    }

    #pragma unroll
    for (int mm = 0; mm < 2; mm++) {
        #pragma unroll
        for (int nn = 0; nn < 8; nn++) {
            const int r = row0 + warpM * 32 + mm * 16 + lm;
            const int c = col0 + warpN * 64 + nn * 8 + 2 * lk;
            float2 o0 = { acc[mm][nn][0] + bias[c], acc[mm][nn][1] + bias[c + 1] };
            float2 o1 = { acc[mm][nn][2] + bias[c], acc[mm][nn][3] + bias[c + 1] };
            *(float2*)&C[(size_t)r * N + c]       = o0;
            *(float2*)&C[(size_t)(r + 8) * N + c] = o1;
        }
    }
}

// ---------------------------------------------------------------------------
// Prep kernel (unchanged)
// ---------------------------------------------------------------------------
__global__ __launch_bounds__(256)
void prep_kernel(const float* __restrict__ qkv,
                 const float* __restrict__ q_gain,
                 const float* __restrict__ k_gain)
{
    const int w = (blockIdx.x * blockDim.x + threadIdx.x) >> 5;
    const int lane = threadIdx.x & 31;
    if (w >= N_B * N_SEQ * NH) return;
    const int h  = w % NH;
    const int bn = w / NH;
    const int n  = bn % N_SEQ;
    const int b  = bn / N_SEQ;

    const float* base = qkv + (size_t)bn * (3 * DM) + h * HD;
    float q0 = base[lane],          q1 = base[lane + 32];
    float k0 = base[DM + lane],     k1 = base[DM + lane + 32];
    float v0 = base[2 * DM + lane], v1 = base[2 * DM + lane + 32];

    const float pos = (lane < 16) ? (float)(n >> 5) : (float)(n & 31);
    const float fr = expf(-((float)(lane & 15) * (1.0f / 16.0f)) * 9.210340371976184f);
    float s, c;
    sincosf(pos * fr, &s, &c);

    const float gq0 = q_gain[lane], gq1 = q_gain[lane + 32];
    const float gk0 = k_gain[lane], gk1 = k_gain[lane + 32];

    float ssq = q0 * q0 + q1 * q1;
    #pragma unroll
    for (int o = 16; o; o >>= 1) ssq += __shfl_xor_sync(0xffffffffu, ssq, o);
    float r = rsqrtf(ssq * (1.0f / 64.0f) + 1e-6f);
    q0 *= r * gq0;  q1 *= r * gq1;
    float t0 = q0 * c - q1 * s;
    float t1 = q1 * c + q0 * s;
    float l2 = t0 * t0 + t1 * t1;
    #pragma unroll
    for (int o = 16; o; o >>= 1) l2 += __shfl_xor_sync(0xffffffffu, l2, o);
    float inv = rsqrtf(l2);
    t0 *= inv;  t1 *= inv;

    const size_t obase = (((size_t)(b * NH + h)) * N_SEQ + n) * HD;
    g_q[obase + lane] = t0;  g_q[obase + lane + 32] = t1;

    ssq = k0 * k0 + k1 * k1;
    #pragma unroll
    for (int o = 16; o; o >>= 1) ssq += __shfl_xor_sync(0xffffffffu, ssq, o);
    r = rsqrtf(ssq * (1.0f / 64.0f) + 1e-6f);
    k0 *= r * gk0;  k1 *= r * gk1;
    t0 = k0 * c - k1 * s;
    t1 = k1 * c + k0 * s;
    l2 = t0 * t0 + t1 * t1;
    #pragma unroll
    for (int o = 16; o; o >>= 1) l2 += __shfl_xor_sync(0xffffffffu, l2, o);
    inv = rsqrtf(l2);
    t0 *= inv;  t1 *= inv;
    g_k[obase + lane] = t0;  g_k[obase + lane + 32] = t1;

    g_v[obase + lane] = v0;  g_v[obase + lane + 32] = v1;
}

// ---------------------------------------------------------------------------
// Tensor-core cosine-sim flash attention (3xTF32 for both matmuls).
// Scores bounded by 8 (unit q,k) => fixed-max softmax: p = exp(8s - 8).
// Block: 256 threads = 8 warps; 128 queries/block; 64-key tiles.
// Warp w owns query rows [w*16, w*16+16). Fragment maps identical to
// sgemm_tf32 (validated). Smem stride 68 -> conflict-free frag loads.
// ---------------------------------------------------------------------------
#define ALD 68
#define ATTN_SMEM_BYTES ((size_t)(128*ALD*2 + 64*ALD*4 + 128*ALD) * 4)

__global__ __launch_bounds__(256)
void attn_tc(float* __restrict__ outp)
{
    extern __shared__ uint32_t sm[];
    uint32_t* Qhi = sm;                  // [128][ALD] q rows x d
    uint32_t* Qlo = Qhi + 128 * ALD;
    uint32_t* Khi = Qlo + 128 * ALD;     // [64][ALD]  key rows x d
    uint32_t* Klo = Khi + 64 * ALD;
    uint32_t* Vhi = Klo + 64 * ALD;      // [64][ALD]  TRANSPOSED: d rows x key
    uint32_t* Vlo = Vhi + 64 * ALD;
    float*    Psh = (float*)(Vlo + 64 * ALD);  // [128][ALD] probs

    const int h = blockIdx.y, b = blockIdx.z;
    const int t = threadIdx.x;
    const int lane = t & 31, warp = t >> 5;
    const int lm = lane >> 2, lk = lane & 3;
    const int qrow0 = warp * 16;
    const size_t bh = ((size_t)b * NH + h) * N_SEQ * HD;

    // ---- Load + split Q tile [128 x 64] ----
    {
        const float4* qp = (const float4*)(g_q + bh + (size_t)blockIdx.x * 128 * HD);
        #pragma unroll
        for (int i = 0; i < 8; i++) {
            const int idx = t + i * 256;            // 2048 float4
            const int r = idx >> 4, c = (idx & 15) * 4;
            float4 v = qp[idx];
            tf32_split(v.x, Qhi[r * ALD + c + 0], Qlo[r * ALD + c + 0]);
            tf32_split(v.y, Qhi[r * ALD + c + 1], Qlo[r * ALD + c + 1]);
            tf32_split(v.z, Qhi[r * ALD + c + 2], Qlo[r * ALD + c + 2]);
            tf32_split(v.w, Qhi[r * ALD + c + 3], Qlo[r * ALD + c + 3]);
        }
    }

    float oacc[8][4] = {};
    float l0 = 0.0f, l1 = 0.0f;

    for (int kt = 0; kt < N_SEQ / 64; kt++) {
        __syncthreads();   // previous iteration's reads done before overwrite
        // ---- Load + split K tile; load + transpose + split V tile ----
        const float4* kp = (const float4*)(g_k + bh + (size_t)kt * 64 * HD);
        const float4* vp = (const float4*)(g_v + bh + (size_t)kt * 64 * HD);
        #pragma unroll
        for (int i = 0; i < 4; i++) {
            const int idx = t + i * 256;            // 1024 float4
            const int r = idx >> 4, c = (idx & 15) * 4;
            float4 kv = kp[idx];
            tf32_split(kv.x, Khi[r * ALD + c + 0], Klo[r * ALD + c + 0]);
            tf32_split(kv.y, Khi[r * ALD + c + 1], Klo[r * ALD + c + 1]);
            tf32_split(kv.z, Khi[r * ALD + c + 2], Klo[r * ALD + c + 2]);
            tf32_split(kv.w, Khi[r * ALD + c + 3], Klo[r * ALD + c + 3]);
            float4 vv = vp[idx];
            tf32_split(vv.x, Vhi[(c + 0) * ALD + r], Vlo[(c + 0) * ALD + r]);
            tf32_split(vv.y, Vhi[(c + 1) * ALD + r], Vlo[(c + 1) * ALD + r]);
            tf32_split(vv.z, Vhi[(c + 2) * ALD + r], Vlo[(c + 2) * ALD + r]);
            tf32_split(vv.w, Vhi[(c + 3) * ALD + r], Vlo[(c + 3) * ALD + r]);
        }
        __syncthreads();

        // ---- S = Q @ K^T  (3xTF32) ----
        float sacc[8][4] = {};
        #pragma unroll
        for (int ks = 0; ks < 8; ks++) {
            const int ab = (qrow0 + lm) * ALD + ks * 8 + lk;
            uint32_t ah0 = Qhi[ab],           ah1 = Qhi[ab + 8 * ALD];
            uint32_t ah2 = Qhi[ab + 4],       ah3 = Qhi[ab + 8 * ALD + 4];
            uint32_t al0 = Qlo[ab],           al1 = Qlo[ab + 8 * ALD];
            uint32_t al2 = Qlo[ab + 4],       al3 = Qlo[ab + 8 * ALD + 4];
            #pragma unroll
            for (int ns = 0; ns < 8; ns++) {
                const int bb = (ns * 8 + lm) * ALD + ks * 8 + lk;
                uint32_t bh0 = Khi[bb], bh1 = Khi[bb + 4];
                uint32_t bl0 = Klo[bb], bl1 = Klo[bb + 4];
                mma_tf32(sacc[ns], ah0, ah1, ah2, ah3, bh0, bh1);
                mma_tf32(sacc[ns], al0, al1, al2, al3, bh0, bh1);
                mma_tf32(sacc[ns], ah0, ah1, ah2, ah3, bl0, bl1);
            }
        }

        // ---- P = exp(8S - 8), accumulate l, stage P in smem ----
        #pragma unroll
        for (int ns = 0; ns < 8; ns++) {
            const float p0 = __expf(8.0f * sacc[ns][0] - 8.0f);
            const float p1 = __expf(8.0f * sacc[ns][1] - 8.0f);
            const float p2 = __expf(8.0f * sacc[ns][2] - 8.0f);
            const float p3 = __expf(8.0f * sacc[ns][3] - 8.0f);
            l0 += p0 + p1;
            l1 += p2 + p3;
            const int pb = (qrow0 + lm) * ALD + ns * 8 + 2 * lk;
            float2 w0 = { p0, p1 }, w1 = { p2, p3 };
            *(float2*)&Psh[pb]           = w0;
            *(float2*)&Psh[pb + 8 * ALD] = w1;
        }
        __syncwarp();   // Psh region is warp-private

        // ---- O += P @ V  (3xTF32) ----
        #pragma unroll
        for (int ks = 0; ks < 8; ks++) {
            const int ab = (qrow0 + lm) * ALD + ks * 8 + lk;
            uint32_t ah0, al0, ah1, al1, ah2, al2, ah3, al3;
            tf32_split(Psh[ab],               ah0, al0);
            tf32_split(Psh[ab + 8 * ALD],     ah1, al1);
            tf32_split(Psh[ab + 4],           ah2, al2);
            tf32_split(Psh[ab + 8 * ALD + 4], ah3, al3);
            #pragma unroll
            for (int ns = 0; ns < 8; ns++) {
                const int bb = (ns * 8 + lm) * ALD + ks * 8 + lk;
                uint32_t vh0 = Vhi[bb], vh1 = Vhi[bb + 4];
                uint32_t vl0 = Vlo[bb], vl1 = Vlo[bb + 4];
                mma_tf32(oacc[ns], ah0, ah1, ah2, ah3, vh0, vh1);
                mma_tf32(oacc[ns], al0, al1, al2, al3, vh0, vh1);
                mma_tf32(oacc[ns], ah0, ah1, ah2, ah3, vl0, vl1);
            }
        }
    }

    // ---- Epilogue: row sums across lane quad, normalize, store ----
    l0 += __shfl_xor_sync(0xffffffffu, l0, 1);
    l0 += __shfl_xor_sync(0xffffffffu, l0, 2);
    l1 += __shfl_xor_sync(0xffffffffu, l1, 1);
    l1 += __shfl_xor_sync(0xffffffffu, l1, 2);
    const float i0 = 1.0f / l0, i1 = 1.0f / l1;

    const int q0 = blockIdx.x * 128 + qrow0 + lm;
    float* o0 = outp + (((size_t)b * N_SEQ + q0) * NH + h) * HD;
    float* o1 = o0 + (size_t)8 * NH * HD;
    #pragma unroll
    for (int ns = 0; ns < 8; ns++) {
        const int c = ns * 8 + 2 * lk;
        float2 w0 = { oacc[ns][0] * i0, oacc[ns][1] * i0 };
        float2 w1 = { oacc[ns][2] * i1, oacc[ns][3] * i1 };
        *(float2*)&o0[c] = w0;
        *(float2*)&o1[c] = w1;
    }
}

// ---------------------------------------------------------------------------
extern "C" void kernel_launch(void* const* d_in, const int* in_sizes, int n_in,
                              void* d_out, int out_size)
{
    const float* x      = (const float*)d_in[0];
    const float* w_qkv  = (const float*)d_in[1];
    const float* b_qkv  = (const float*)d_in[2];
    const float* q_gain = (const float*)d_in[3];
    const float* k_gain = (const float*)d_in[4];
    const float* w_out  = (const float*)d_in[5];
    const float* b_out  = (const float*)d_in[6];
    float* out = (float*)d_out;

    float *qkv_p, *o_p;
    cudaGetSymbolAddress((void**)&qkv_p, g_qkv);
    cudaGetSymbolAddress((void**)&o_p, g_o);

    const int M = N_B * N_SEQ;  // 8192

    // 1) QKV projection (tf32 tensor cores)
    sgemm_tf32<<<dim3((3 * DM) / 128, M / 128), 256>>>(x, w_qkv, b_qkv, qkv_p, M, 3 * DM, DM);

    // 2) RMSNorm + RoPE + L2-norm + head transpose
    prep_kernel<<<(N_B * N_SEQ * NH * 32) / 256, 256>>>(qkv_p, q_gain, k_gain);

    // 3) Tensor-core cosine-sim attention
    cudaFuncSetAttribute(attn_tc, cudaFuncAttributeMaxDynamicSharedMemorySize,
                         (int)ATTN_SMEM_BYTES);
    attn_tc<<<dim3(N_SEQ / 128, NH, N_B), 256, ATTN_SMEM_BYTES>>>(o_p);

    // 4) Output projection (tf32 tensor cores)
    sgemm_tf32<<<dim3(DM / 128, M / 128), 256>>>(o_p, w_out, b_out, out, M, DM, DM);
}

// round 10
// speedup vs baseline: 3.1882x; 1.1447x over previous
#include <cuda_runtime.h>
#include <math.h>
#include <stdint.h>

#define N_B   8
#define N_SEQ 1024
#define DM    1024
#define NH    16
#define HD    64

// Scratch (allocation-free: device globals)
__device__ float g_qkv[(size_t)N_B * N_SEQ * 3 * DM];
__device__ float g_q[(size_t)N_B * NH * N_SEQ * HD];
__device__ float g_k[(size_t)N_B * NH * N_SEQ * HD];
__device__ float g_v[(size_t)N_B * NH * N_SEQ * HD];
__device__ float g_o[(size_t)N_B * N_SEQ * DM];

// ---------------------------------------------------------------------------
// tf32 / async helpers
// ---------------------------------------------------------------------------
__device__ __forceinline__ uint32_t f2tf32(float x) {
    uint32_t r;
    asm("cvt.rna.tf32.f32 %0, %1;" : "=r"(r) : "f"(x));
    return r;
}
__device__ __forceinline__ void tf32_split(float x, uint32_t& hi, uint32_t& lo) {
    hi = f2tf32(x);
    lo = f2tf32(x - __uint_as_float(hi));
}
__device__ __forceinline__ void mma_tf32(float c[4],
                                         uint32_t a0, uint32_t a1, uint32_t a2, uint32_t a3,
                                         uint32_t b0, uint32_t b1) {
    asm volatile(
        "mma.sync.aligned.m16n8k8.row.col.f32.tf32.tf32.f32 "
        "{%0,%1,%2,%3}, {%4,%5,%6,%7}, {%8,%9}, {%0,%1,%2,%3};\n"
        : "+f"(c[0]), "+f"(c[1]), "+f"(c[2]), "+f"(c[3])
        : "r"(a0), "r"(a1), "r"(a2), "r"(a3), "r"(b0), "r"(b1));
}
__device__ __forceinline__ void cp_async16(void* smem_dst, const void* gmem_src) {
    uint32_t s = (uint32_t)__cvta_generic_to_shared(smem_dst);
    asm volatile("cp.async.cg.shared.global [%0], [%1], 16;\n" :: "r"(s), "l"(gmem_src));
}
#define CP_COMMIT() asm volatile("cp.async.commit_group;\n" ::: "memory")
#define CP_WAIT(n)  asm volatile("cp.async.wait_group %0;\n" :: "n"(n) : "memory")

// ---------------------------------------------------------------------------
// TF32 tensor-core GEMM v2: C = A@B + bias.
// 128x128 tile, BK=16, 256 threads, 8 warps (4x2), warp tile 32x64.
// 2-stage cp.async double buffer: raw fp32 tiles global->smem (no register
// pass-through), tf32 conversion at fragment load (fma pipe is idle anyway).
// A smem [m][k] LDK=20 pad, B smem [k][n] LDB=136 pad: both conflict-free.
// ---------------------------------------------------------------------------
#define LDK 20
#define LDB 136
#define ASZ (128 * LDK)
#define BSZ (16 * LDB)

__global__ __launch_bounds__(256)
void sgemm_tf32(const float* __restrict__ A, const float* __restrict__ B,
                const float* __restrict__ bias, float* __restrict__ C,
                int M, int N, int K)
{
    __shared__ float As2[2][ASZ];
    __shared__ float Bs2[2][BSZ];

    const int tid  = threadIdx.x;
    const int lane = tid & 31;
    const int warp = tid >> 5;
    const int warpM = warp & 3;
    const int warpN = warp >> 2;
    const int lm = lane >> 2;
    const int lk = lane & 3;

    const int row0 = blockIdx.y * 128;
    const int col0 = blockIdx.x * 128;

    // cp.async chunk mapping (2 x 16B per thread for each of A, B)
    const int a_row0 = tid >> 2,  a_kc = (tid & 3) * 4;     // A: chunks tid, tid+256
    const int b_kr0  = tid >> 5,  b_nc = (tid & 31) * 4;    // B: chunks tid, tid+256

    float acc[2][8][4] = {};

    // Prologue: tile 0
    {
        cp_async16(&As2[0][a_row0 * LDK + a_kc],
                   A + (size_t)(row0 + a_row0) * K + a_kc);
        cp_async16(&As2[0][(a_row0 + 64) * LDK + a_kc],
                   A + (size_t)(row0 + a_row0 + 64) * K + a_kc);
        cp_async16(&Bs2[0][b_kr0 * LDB + b_nc],
                   B + (size_t)b_kr0 * N + col0 + b_nc);
        cp_async16(&Bs2[0][(b_kr0 + 8) * LDB + b_nc],
                   B + (size_t)(b_kr0 + 8) * N + col0 + b_nc);
        CP_COMMIT();
    }

    const int ntiles = K >> 4;
    for (int it = 0; it < ntiles; it++) {
        const int buf = it & 1;
        if (it + 1 < ntiles) {
            const int k0 = (it + 1) << 4;
            float* Ad = As2[buf ^ 1];
            float* Bd = Bs2[buf ^ 1];
            cp_async16(&Ad[a_row0 * LDK + a_kc],
                       A + (size_t)(row0 + a_row0) * K + k0 + a_kc);
            cp_async16(&Ad[(a_row0 + 64) * LDK + a_kc],
                       A + (size_t)(row0 + a_row0 + 64) * K + k0 + a_kc);
            cp_async16(&Bd[b_kr0 * LDB + b_nc],
                       B + (size_t)(k0 + b_kr0) * N + col0 + b_nc);
            cp_async16(&Bd[(b_kr0 + 8) * LDB + b_nc],
                       B + (size_t)(k0 + b_kr0 + 8) * N + col0 + b_nc);
            CP_COMMIT();
            CP_WAIT(1);          // current tile's group complete
        } else {
            CP_WAIT(0);
        }
        __syncthreads();

        const float* Asb = As2[buf];
        const float* Bsb = Bs2[buf];
        #pragma unroll
        for (int ks = 0; ks < 2; ks++) {
            uint32_t af[2][4];
            #pragma unroll
            for (int mm = 0; mm < 2; mm++) {
                const int mb = warpM * 32 + mm * 16 + lm;
                af[mm][0] = f2tf32(Asb[mb * LDK + ks * 8 + lk]);
                af[mm][1] = f2tf32(Asb[(mb + 8) * LDK + ks * 8 + lk]);
                af[mm][2] = f2tf32(Asb[mb * LDK + ks * 8 + lk + 4]);
                af[mm][3] = f2tf32(Asb[(mb + 8) * LDK + ks * 8 + lk + 4]);
            }
            uint32_t bf[8][2];
            #pragma unroll
            for (int nn = 0; nn < 8; nn++) {
                const int nb = warpN * 64 + nn * 8 + lm;
                bf[nn][0] = f2tf32(Bsb[(ks * 8 + lk) * LDB + nb]);
                bf[nn][1] = f2tf32(Bsb[(ks * 8 + lk + 4) * LDB + nb]);
            }
            #pragma unroll
            for (int mm = 0; mm < 2; mm++)
                #pragma unroll
                for (int nn = 0; nn < 8; nn++)
                    mma_tf32(acc[mm][nn], af[mm][0], af[mm][1], af[mm][2], af[mm][3],
                             bf[nn][0], bf[nn][1]);
        }
        __syncthreads();    // all reads of buf done before it is refilled
    }

    #pragma unroll
    for (int mm = 0; mm < 2; mm++) {
        #pragma unroll
        for (int nn = 0; nn < 8; nn++) {
            const int r = row0 + warpM * 32 + mm * 16 + lm;
            const int c = col0 + warpN * 64 + nn * 8 + 2 * lk;
            float2 o0 = { acc[mm][nn][0] + bias[c], acc[mm][nn][1] + bias[c + 1] };
            float2 o1 = { acc[mm][nn][2] + bias[c], acc[mm][nn][3] + bias[c + 1] };
            *(float2*)&C[(size_t)r * N + c]       = o0;
            *(float2*)&C[(size_t)(r + 8) * N + c] = o1;
        }
    }
}

// ---------------------------------------------------------------------------
// Prep kernel (unchanged)
// ---------------------------------------------------------------------------
__global__ __launch_bounds__(256)
void prep_kernel(const float* __restrict__ qkv,
                 const float* __restrict__ q_gain,
                 const float* __restrict__ k_gain)
{
    const int w = (blockIdx.x * blockDim.x + threadIdx.x) >> 5;
    const int lane = threadIdx.x & 31;
    if (w >= N_B * N_SEQ * NH) return;
    const int h  = w % NH;
    const int bn = w / NH;
    const int n  = bn % N_SEQ;
    const int b  = bn / N_SEQ;

    const float* base = qkv + (size_t)bn * (3 * DM) + h * HD;
    float q0 = base[lane],          q1 = base[lane + 32];
    float k0 = base[DM + lane],     k1 = base[DM + lane + 32];
    float v0 = base[2 * DM + lane], v1 = base[2 * DM + lane + 32];

    const float pos = (lane < 16) ? (float)(n >> 5) : (float)(n & 31);
    const float fr = expf(-((float)(lane & 15) * (1.0f / 16.0f)) * 9.210340371976184f);
    float s, c;
    sincosf(pos * fr, &s, &c);

    const float gq0 = q_gain[lane], gq1 = q_gain[lane + 32];
    const float gk0 = k_gain[lane], gk1 = k_gain[lane + 32];

    float ssq = q0 * q0 + q1 * q1;
    #pragma unroll
    for (int o = 16; o; o >>= 1) ssq += __shfl_xor_sync(0xffffffffu, ssq, o);
    float r = rsqrtf(ssq * (1.0f / 64.0f) + 1e-6f);
    q0 *= r * gq0;  q1 *= r * gq1;
    float t0 = q0 * c - q1 * s;
    float t1 = q1 * c + q0 * s;
    float l2 = t0 * t0 + t1 * t1;
    #pragma unroll
    for (int o = 16; o; o >>= 1) l2 += __shfl_xor_sync(0xffffffffu, l2, o);
    float inv = rsqrtf(l2);
    t0 *= inv;  t1 *= inv;

    const size_t obase = (((size_t)(b * NH + h)) * N_SEQ + n) * HD;
    g_q[obase + lane] = t0;  g_q[obase + lane + 32] = t1;

    ssq = k0 * k0 + k1 * k1;
    #pragma unroll
    for (int o = 16; o; o >>= 1) ssq += __shfl_xor_sync(0xffffffffu, ssq, o);
    r = rsqrtf(ssq * (1.0f / 64.0f) + 1e-6f);
    k0 *= r * gk0;  k1 *= r * gk1;
    t0 = k0 * c - k1 * s;
    t1 = k1 * c + k0 * s;
    l2 = t0 * t0 + t1 * t1;
    #pragma unroll
    for (int o = 16; o; o >>= 1) l2 += __shfl_xor_sync(0xffffffffu, l2, o);
    inv = rsqrtf(l2);
    t0 *= inv;  t1 *= inv;
    g_k[obase + lane] = t0;  g_k[obase + lane + 32] = t1;

    g_v[obase + lane] = v0;  g_v[obase + lane + 32] = v1;
}

// ---------------------------------------------------------------------------
// Tensor-core cosine-sim flash attention (3xTF32, unchanged from R9 winner)
// ---------------------------------------------------------------------------
#define ALD 68
#define ATTN_SMEM_BYTES ((size_t)(128*ALD*2 + 64*ALD*4 + 128*ALD) * 4)

__global__ __launch_bounds__(256)
void attn_tc(float* __restrict__ outp)
{
    extern __shared__ uint32_t sm[];
    uint32_t* Qhi = sm;
    uint32_t* Qlo = Qhi + 128 * ALD;
    uint32_t* Khi = Qlo + 128 * ALD;
    uint32_t* Klo = Khi + 64 * ALD;
    uint32_t* Vhi = Klo + 64 * ALD;
    uint32_t* Vlo = Vhi + 64 * ALD;
    float*    Psh = (float*)(Vlo + 64 * ALD);

    const int h = blockIdx.y, b = blockIdx.z;
    const int t = threadIdx.x;
    const int lane = t & 31, warp = t >> 5;
    const int lm = lane >> 2, lk = lane & 3;
    const int qrow0 = warp * 16;
    const size_t bh = ((size_t)b * NH + h) * N_SEQ * HD;

    {
        const float4* qp = (const float4*)(g_q + bh + (size_t)blockIdx.x * 128 * HD);
        #pragma unroll
        for (int i = 0; i < 8; i++) {
            const int idx = t + i * 256;
            const int r = idx >> 4, c = (idx & 15) * 4;
            float4 v = qp[idx];
            tf32_split(v.x, Qhi[r * ALD + c + 0], Qlo[r * ALD + c + 0]);
            tf32_split(v.y, Qhi[r * ALD + c + 1], Qlo[r * ALD + c + 1]);
            tf32_split(v.z, Qhi[r * ALD + c + 2], Qlo[r * ALD + c + 2]);
            tf32_split(v.w, Qhi[r * ALD + c + 3], Qlo[r * ALD + c + 3]);
        }
    }

    float oacc[8][4] = {};
    float l0 = 0.0f, l1 = 0.0f;

    for (int kt = 0; kt < N_SEQ / 64; kt++) {
        __syncthreads();
        const float4* kp = (const float4*)(g_k + bh + (size_t)kt * 64 * HD);
        const float4* vp = (const float4*)(g_v + bh + (size_t)kt * 64 * HD);
        #pragma unroll
        for (int i = 0; i < 4; i++) {
            const int idx = t + i * 256;
            const int r = idx >> 4, c = (idx & 15) * 4;
            float4 kv = kp[idx];
            tf32_split(kv.x, Khi[r * ALD + c + 0], Klo[r * ALD + c + 0]);
            tf32_split(kv.y, Khi[r * ALD + c + 1], Klo[r * ALD + c + 1]);
            tf32_split(kv.z, Khi[r * ALD + c + 2], Klo[r * ALD + c + 2]);
            tf32_split(kv.w, Khi[r * ALD + c + 3], Klo[r * ALD + c + 3]);
            float4 vv = vp[idx];
            tf32_split(vv.x, Vhi[(c + 0) * ALD + r], Vlo[(c + 0) * ALD + r]);
            tf32_split(vv.y, Vhi[(c + 1) * ALD + r], Vlo[(c + 1) * ALD + r]);
            tf32_split(vv.z, Vhi[(c + 2) * ALD + r], Vlo[(c + 2) * ALD + r]);
            tf32_split(vv.w, Vhi[(c + 3) * ALD + r], Vlo[(c + 3) * ALD + r]);
        }
        __syncthreads();

        float sacc[8][4] = {};
        #pragma unroll
        for (int ks = 0; ks < 8; ks++) {
            const int ab = (qrow0 + lm) * ALD + ks * 8 + lk;
            uint32_t ah0 = Qhi[ab],           ah1 = Qhi[ab + 8 * ALD];
            uint32_t ah2 = Qhi[ab + 4],       ah3 = Qhi[ab + 8 * ALD + 4];
            uint32_t al0 = Qlo[ab],           al1 = Qlo[ab + 8 * ALD];
            uint32_t al2 = Qlo[ab + 4],       al3 = Qlo[ab + 8 * ALD + 4];
            #pragma unroll
            for (int ns = 0; ns < 8; ns++) {
                const int bb = (ns * 8 + lm) * ALD + ks * 8 + lk;
                uint32_t bh0 = Khi[bb], bh1 = Khi[bb + 4];
                uint32_t bl0 = Klo[bb], bl1 = Klo[bb + 4];
                mma_tf32(sacc[ns], ah0, ah1, ah2, ah3, bh0, bh1);
                mma_tf32(sacc[ns], al0, al1, al2, al3, bh0, bh1);
                mma_tf32(sacc[ns], ah0, ah1, ah2, ah3, bl0, bl1);
            }
        }

        #pragma unroll
        for (int ns = 0; ns < 8; ns++) {
            const float p0 = __expf(8.0f * sacc[ns][0] - 8.0f);
            const float p1 = __expf(8.0f * sacc[ns][1] - 8.0f);
            const float p2 = __expf(8.0f * sacc[ns][2] - 8.0f);
            const float p3 = __expf(8.0f * sacc[ns][3] - 8.0f);
            l0 += p0 + p1;
            l1 += p2 + p3;
            const int pb = (qrow0 + lm) * ALD + ns * 8 + 2 * lk;
            float2 w0 = { p0, p1 }, w1 = { p2, p3 };
            *(float2*)&Psh[pb]           = w0;
            *(float2*)&Psh[pb + 8 * ALD] = w1;
        }
        __syncwarp();

        #pragma unroll
        for (int ks = 0; ks < 8; ks++) {
            const int ab = (qrow0 + lm) * ALD + ks * 8 + lk;
            uint32_t ah0, al0, ah1, al1, ah2, al2, ah3, al3;
            tf32_split(Psh[ab],               ah0, al0);
            tf32_split(Psh[ab + 8 * ALD],     ah1, al1);
            tf32_split(Psh[ab + 4],           ah2, al2);
            tf32_split(Psh[ab + 8 * ALD + 4], ah3, al3);
            #pragma unroll
            for (int ns = 0; ns < 8; ns++) {
                const int bb = (ns * 8 + lm) * ALD + ks * 8 + lk;
                uint32_t vh0 = Vhi[bb], vh1 = Vhi[bb + 4];
                uint32_t vl0 = Vlo[bb], vl1 = Vlo[bb + 4];
                mma_tf32(oacc[ns], ah0, ah1, ah2, ah3, vh0, vh1);
                mma_tf32(oacc[ns], al0, al1, al2, al3, vh0, vh1);
                mma_tf32(oacc[ns], ah0, ah1, ah2, ah3, vl0, vl1);
            }
        }
    }

    l0 += __shfl_xor_sync(0xffffffffu, l0, 1);
    l0 += __shfl_xor_sync(0xffffffffu, l0, 2);
    l1 += __shfl_xor_sync(0xffffffffu, l1, 1);
    l1 += __shfl_xor_sync(0xffffffffu, l1, 2);
    const float i0 = 1.0f / l0, i1 = 1.0f / l1;

    const int q0 = blockIdx.x * 128 + qrow0 + lm;
    float* o0 = outp + (((size_t)b * N_SEQ + q0) * NH + h) * HD;
    float* o1 = o0 + (size_t)8 * NH * HD;
    #pragma unroll
    for (int ns = 0; ns < 8; ns++) {
        const int c = ns * 8 + 2 * lk;
        float2 w0 = { oacc[ns][0] * i0, oacc[ns][1] * i0 };
        float2 w1 = { oacc[ns][2] * i1, oacc[ns][3] * i1 };
        *(float2*)&o0[c] = w0;
        *(float2*)&o1[c] = w1;
    }
}

// ---------------------------------------------------------------------------
extern "C" void kernel_launch(void* const* d_in, const int* in_sizes, int n_in,
                              void* d_out, int out_size)
{
    const float* x      = (const float*)d_in[0];
    const float* w_qkv  = (const float*)d_in[1];
    const float* b_qkv  = (const float*)d_in[2];
    const float* q_gain = (const float*)d_in[3];
    const float* k_gain = (const float*)d_in[4];
    const float* w_out  = (const float*)d_in[5];
    const float* b_out  = (const float*)d_in[6];
    float* out = (float*)d_out;

    float *qkv_p, *o_p;
    cudaGetSymbolAddress((void**)&qkv_p, g_qkv);
    cudaGetSymbolAddress((void**)&o_p, g_o);

    const int M = N_B * N_SEQ;  // 8192

    // 1) QKV projection (tf32 tensor cores, cp.async pipelined)
    sgemm_tf32<<<dim3((3 * DM) / 128, M / 128), 256>>>(x, w_qkv, b_qkv, qkv_p, M, 3 * DM, DM);

    // 2) RMSNorm + RoPE + L2-norm + head transpose
    prep_kernel<<<(N_B * N_SEQ * NH * 32) / 256, 256>>>(qkv_p, q_gain, k_gain);

    // 3) Tensor-core cosine-sim attention
    cudaFuncSetAttribute(attn_tc, cudaFuncAttributeMaxDynamicSharedMemorySize,
                         (int)ATTN_SMEM_BYTES);
    attn_tc<<<dim3(N_SEQ / 128, NH, N_B), 256, ATTN_SMEM_BYTES>>>(o_p);

    // 4) Output projection (tf32 tensor cores, cp.async pipelined)
    sgemm_tf32<<<dim3(DM / 128, M / 128), 256>>>(o_p, w_out, b_out, out, M, DM, DM);
}

// round 11
// speedup vs baseline: 4.2951x; 1.3472x over previous
#include <cuda_runtime.h>
#include <cuda_bf16.h>
#include <math.h>
#include <stdint.h>

#define N_B   8
#define N_SEQ 1024
#define DM    1024
#define NH    16
#define HD    64

// Scratch (allocation-free: device globals)
__device__ float g_qkv[(size_t)N_B * N_SEQ * 3 * DM];
__device__ float g_q[(size_t)N_B * NH * N_SEQ * HD];
__device__ float g_k[(size_t)N_B * NH * N_SEQ * HD];
__device__ float g_v[(size_t)N_B * NH * N_SEQ * HD];
__device__ float g_o[(size_t)N_B * N_SEQ * DM];

// ---------------------------------------------------------------------------
// tf32 / bf16 / async helpers
// ---------------------------------------------------------------------------
__device__ __forceinline__ uint32_t f2tf32(float x) {
    uint32_t r;
    asm("cvt.rna.tf32.f32 %0, %1;" : "=r"(r) : "f"(x));
    return r;
}
__device__ __forceinline__ void mma_tf32(float c[4],
                                         uint32_t a0, uint32_t a1, uint32_t a2, uint32_t a3,
                                         uint32_t b0, uint32_t b1) {
    asm volatile(
        "mma.sync.aligned.m16n8k8.row.col.f32.tf32.tf32.f32 "
        "{%0,%1,%2,%3}, {%4,%5,%6,%7}, {%8,%9}, {%0,%1,%2,%3};\n"
        : "+f"(c[0]), "+f"(c[1]), "+f"(c[2]), "+f"(c[3])
        : "r"(a0), "r"(a1), "r"(a2), "r"(a3), "r"(b0), "r"(b1));
}
__device__ __forceinline__ void mma_bf16(float c[4],
                                         uint32_t a0, uint32_t a1, uint32_t a2, uint32_t a3,
                                         uint32_t b0, uint32_t b1) {
    asm volatile(
        "mma.sync.aligned.m16n8k16.row.col.f32.bf16.bf16.f32 "
        "{%0,%1,%2,%3}, {%4,%5,%6,%7}, {%8,%9}, {%0,%1,%2,%3};\n"
        : "+f"(c[0]), "+f"(c[1]), "+f"(c[2]), "+f"(c[3])
        : "r"(a0), "r"(a1), "r"(a2), "r"(a3), "r"(b0), "r"(b1));
}
// pack two floats into bf16x2 (lo half = x0 = even-k element)
__device__ __forceinline__ uint32_t bfpack(float x0, float x1) {
    uint32_t r;
    asm("cvt.rn.bf16x2.f32 %0, %1, %2;" : "=r"(r) : "f"(x1), "f"(x0));
    return r;
}
// hi/lo split of a k-pair: hi = bf16 rounding, lo = residual in bf16
__device__ __forceinline__ void bf_split2(float x0, float x1, uint32_t& hi, uint32_t& lo) {
    hi = bfpack(x0, x1);
    __nv_bfloat162 h2 = *reinterpret_cast<__nv_bfloat162*>(&hi);
    lo = bfpack(x0 - __low2float(h2), x1 - __high2float(h2));
}
__device__ __forceinline__ void cp_async16(void* smem_dst, const void* gmem_src) {
    uint32_t s = (uint32_t)__cvta_generic_to_shared(smem_dst);
    asm volatile("cp.async.cg.shared.global [%0], [%1], 16;\n" :: "r"(s), "l"(gmem_src));
}
#define CP_COMMIT() asm volatile("cp.async.commit_group;\n" ::: "memory")
#define CP_WAIT(n)  asm volatile("cp.async.wait_group %0;\n" :: "n"(n) : "memory")

// ---------------------------------------------------------------------------
// TF32 tensor-core GEMM (unchanged from R10 winner)
// ---------------------------------------------------------------------------
#define LDK 20
#define LDB 136
#define ASZ (128 * LDK)
#define BSZ (16 * LDB)

__global__ __launch_bounds__(256)
void sgemm_tf32(const float* __restrict__ A, const float* __restrict__ B,
                const float* __restrict__ bias, float* __restrict__ C,
                int M, int N, int K)
{
    __shared__ float As2[2][ASZ];
    __shared__ float Bs2[2][BSZ];

    const int tid  = threadIdx.x;
    const int lane = tid & 31;
    const int warp = tid >> 5;
    const int warpM = warp & 3;
    const int warpN = warp >> 2;
    const int lm = lane >> 2;
    const int lk = lane & 3;

    const int row0 = blockIdx.y * 128;
    const int col0 = blockIdx.x * 128;

    const int a_row0 = tid >> 2,  a_kc = (tid & 3) * 4;
    const int b_kr0  = tid >> 5,  b_nc = (tid & 31) * 4;

    float acc[2][8][4] = {};

    {
        cp_async16(&As2[0][a_row0 * LDK + a_kc],
                   A + (size_t)(row0 + a_row0) * K + a_kc);
        cp_async16(&As2[0][(a_row0 + 64) * LDK + a_kc],
                   A + (size_t)(row0 + a_row0 + 64) * K + a_kc);
        cp_async16(&Bs2[0][b_kr0 * LDB + b_nc],
                   B + (size_t)b_kr0 * N + col0 + b_nc);
        cp_async16(&Bs2[0][(b_kr0 + 8) * LDB + b_nc],
                   B + (size_t)(b_kr0 + 8) * N + col0 + b_nc);
        CP_COMMIT();
    }

    const int ntiles = K >> 4;
    for (int it = 0; it < ntiles; it++) {
        const int buf = it & 1;
        if (it + 1 < ntiles) {
            const int k0 = (it + 1) << 4;
            float* Ad = As2[buf ^ 1];
            float* Bd = Bs2[buf ^ 1];
            cp_async16(&Ad[a_row0 * LDK + a_kc],
                       A + (size_t)(row0 + a_row0) * K + k0 + a_kc);
            cp_async16(&Ad[(a_row0 + 64) * LDK + a_kc],
                       A + (size_t)(row0 + a_row0 + 64) * K + k0 + a_kc);
            cp_async16(&Bd[b_kr0 * LDB + b_nc],
                       B + (size_t)(k0 + b_kr0) * N + col0 + b_nc);
            cp_async16(&Bd[(b_kr0 + 8) * LDB + b_nc],
                       B + (size_t)(k0 + b_kr0 + 8) * N + col0 + b_nc);
            CP_COMMIT();
            CP_WAIT(1);
        } else {
            CP_WAIT(0);
        }
        __syncthreads();

        const float* Asb = As2[buf];
        const float* Bsb = Bs2[buf];
        #pragma unroll
        for (int ks = 0; ks < 2; ks++) {
            uint32_t af[2][4];
            #pragma unroll
            for (int mm = 0; mm < 2; mm++) {
                const int mb = warpM * 32 + mm * 16 + lm;
                af[mm][0] = f2tf32(Asb[mb * LDK + ks * 8 + lk]);
                af[mm][1] = f2tf32(Asb[(mb + 8) * LDK + ks * 8 + lk]);
                af[mm][2] = f2tf32(Asb[mb * LDK + ks * 8 + lk + 4]);
                af[mm][3] = f2tf32(Asb[(mb + 8) * LDK + ks * 8 + lk + 4]);
            }
            uint32_t bf[8][2];
            #pragma unroll
            for (int nn = 0; nn < 8; nn++) {
                const int nb = warpN * 64 + nn * 8 + lm;
                bf[nn][0] = f2tf32(Bsb[(ks * 8 + lk) * LDB + nb]);
                bf[nn][1] = f2tf32(Bsb[(ks * 8 + lk + 4) * LDB + nb]);
            }
            #pragma unroll
            for (int mm = 0; mm < 2; mm++)
                #pragma unroll
                for (int nn = 0; nn < 8; nn++)
                    mma_tf32(acc[mm][nn], af[mm][0], af[mm][1], af[mm][2], af[mm][3],
                             bf[nn][0], bf[nn][1]);
        }
        __syncthreads();
    }

    #pragma unroll
    for (int mm = 0; mm < 2; mm++) {
        #pragma unroll
        for (int nn = 0; nn < 8; nn++) {
            const int r = row0 + warpM * 32 + mm * 16 + lm;
            const int c = col0 + warpN * 64 + nn * 8 + 2 * lk;
            float2 o0 = { acc[mm][nn][0] + bias[c], acc[mm][nn][1] + bias[c + 1] };
            float2 o1 = { acc[mm][nn][2] + bias[c], acc[mm][nn][3] + bias[c + 1] };
            *(float2*)&C[(size_t)r * N + c]       = o0;
            *(float2*)&C[(size_t)(r + 8) * N + c] = o1;
        }
    }
}

// ---------------------------------------------------------------------------
// Prep kernel (unchanged)
// ---------------------------------------------------------------------------
__global__ __launch_bounds__(256)
void prep_kernel(const float* __restrict__ qkv,
                 const float* __restrict__ q_gain,
                 const float* __restrict__ k_gain)
{
    const int w = (blockIdx.x * blockDim.x + threadIdx.x) >> 5;
    const int lane = threadIdx.x & 31;
    if (w >= N_B * N_SEQ * NH) return;
    const int h  = w % NH;
    const int bn = w / NH;
    const int n  = bn % N_SEQ;
    const int b  = bn / N_SEQ;

    const float* base = qkv + (size_t)bn * (3 * DM) + h * HD;
    float q0 = base[lane],          q1 = base[lane + 32];
    float k0 = base[DM + lane],     k1 = base[DM + lane + 32];
    float v0 = base[2 * DM + lane], v1 = base[2 * DM + lane + 32];

    const float pos = (lane < 16) ? (float)(n >> 5) : (float)(n & 31);
    const float fr = expf(-((float)(lane & 15) * (1.0f / 16.0f)) * 9.210340371976184f);
    float s, c;
    sincosf(pos * fr, &s, &c);

    const float gq0 = q_gain[lane], gq1 = q_gain[lane + 32];
    const float gk0 = k_gain[lane], gk1 = k_gain[lane + 32];

    float ssq = q0 * q0 + q1 * q1;
    #pragma unroll
    for (int o = 16; o; o >>= 1) ssq += __shfl_xor_sync(0xffffffffu, ssq, o);
    float r = rsqrtf(ssq * (1.0f / 64.0f) + 1e-6f);
    q0 *= r * gq0;  q1 *= r * gq1;
    float t0 = q0 * c - q1 * s;
    float t1 = q1 * c + q0 * s;
    float l2 = t0 * t0 + t1 * t1;
    #pragma unroll
    for (int o = 16; o; o >>= 1) l2 += __shfl_xor_sync(0xffffffffu, l2, o);
    float inv = rsqrtf(l2);
    t0 *= inv;  t1 *= inv;

    const size_t obase = (((size_t)(b * NH + h)) * N_SEQ + n) * HD;
    g_q[obase + lane] = t0;  g_q[obase + lane + 32] = t1;

    ssq = k0 * k0 + k1 * k1;
    #pragma unroll
    for (int o = 16; o; o >>= 1) ssq += __shfl_xor_sync(0xffffffffu, ssq, o);
    r = rsqrtf(ssq * (1.0f / 64.0f) + 1e-6f);
    k0 *= r * gk0;  k1 *= r * gk1;
    t0 = k0 * c - k1 * s;
    t1 = k1 * c + k0 * s;
    l2 = t0 * t0 + t1 * t1;
    #pragma unroll
    for (int o = 16; o; o >>= 1) l2 += __shfl_xor_sync(0xffffffffu, l2, o);
    inv = rsqrtf(l2);
    t0 *= inv;  t1 *= inv;
    g_k[obase + lane] = t0;  g_k[obase + lane + 32] = t1;

    g_v[obase + lane] = v0;  g_v[obase + lane + 32] = v1;
}

// ---------------------------------------------------------------------------
// Tensor-core cosine-sim flash attention, 3xBF16 compensated (m16n8k16).
// All operands stored as bf16x2 k-pairs, hi and lo planes, pair-stride 36
// (conflict-free fragment reads: addr mod 32 = 4*lm + lk, all distinct).
// Fixed-max softmax p = exp(8s - 8). Smem 110.6 KB -> 2 blocks/SM.
// ---------------------------------------------------------------------------
#define PLD 36
#define ATTN_SMEM_BYTES ((size_t)(128*PLD*2 + 64*PLD*4 + 128*PLD*2) * 4)

__global__ __launch_bounds__(256, 2)
void attn_tc(float* __restrict__ outp)
{
    extern __shared__ uint32_t sm[];
    uint32_t* Qhi = sm;                   // [128][PLD] q rows x 32 k-pairs
    uint32_t* Qlo = Qhi + 128 * PLD;
    uint32_t* Khi = Qlo + 128 * PLD;      // [64][PLD]  key rows x 32 d-pairs
    uint32_t* Klo = Khi + 64 * PLD;
    uint32_t* Vhi = Klo + 64 * PLD;       // [64][PLD]  d rows x 32 key-pairs
    uint32_t* Vlo = Vhi + 64 * PLD;
    uint32_t* Phi = Vlo + 64 * PLD;       // [128][PLD] q rows x 32 key-pairs
    uint32_t* Plo = Phi + 128 * PLD;

    const int h = blockIdx.y, b = blockIdx.z;
    const int t = threadIdx.x;
    const int lane = t & 31, warp = t >> 5;
    const int lm = lane >> 2, lk = lane & 3;
    const int qrow0 = warp * 16;
    const size_t bh = ((size_t)b * NH + h) * N_SEQ * HD;

    // ---- Load + split Q tile [128 x 64] into bf16x2 pairs ----
    {
        const float4* qp = (const float4*)(g_q + bh + (size_t)blockIdx.x * 128 * HD);
        #pragma unroll
        for (int i = 0; i < 8; i++) {
            const int idx = t + i * 256;            // 2048 float4
            const int r = idx >> 4, pc = (idx & 15) * 2;
            float4 v = qp[idx];
            bf_split2(v.x, v.y, Qhi[r * PLD + pc],     Qlo[r * PLD + pc]);
            bf_split2(v.z, v.w, Qhi[r * PLD + pc + 1], Qlo[r * PLD + pc + 1]);
        }
    }

    float oacc[8][4] = {};
    float l0 = 0.0f, l1 = 0.0f;

    for (int kt = 0; kt < N_SEQ / 64; kt++) {
        __syncthreads();
        // ---- K tile [64 keys x 64 d] -> pairs along d ----
        const float4* kp4 = (const float4*)(g_k + bh + (size_t)kt * 64 * HD);
        #pragma unroll
        for (int i = 0; i < 4; i++) {
            const int idx = t + i * 256;            // 1024 float4
            const int r = idx >> 4, pc = (idx & 15) * 2;
            float4 kv = kp4[idx];
            bf_split2(kv.x, kv.y, Khi[r * PLD + pc],     Klo[r * PLD + pc]);
            bf_split2(kv.z, kv.w, Khi[r * PLD + pc + 1], Klo[r * PLD + pc + 1]);
        }
        // ---- V tile -> transposed [d][key-pair] ----
        const float4* vp4 = (const float4*)(g_v + bh + (size_t)kt * 64 * HD);
        #pragma unroll
        for (int i = 0; i < 2; i++) {
            const int id = t + i * 256;             // 512 items
            const int kpair = id & 31, cg = id >> 5;   // key pair, col group (4 d's)
            float4 va = vp4[(2 * kpair) * 16 + cg];
            float4 vb = vp4[(2 * kpair + 1) * 16 + cg];
            bf_split2(va.x, vb.x, Vhi[(4 * cg + 0) * PLD + kpair], Vlo[(4 * cg + 0) * PLD + kpair]);
            bf_split2(va.y, vb.y, Vhi[(4 * cg + 1) * PLD + kpair], Vlo[(4 * cg + 1) * PLD + kpair]);
            bf_split2(va.z, vb.z, Vhi[(4 * cg + 2) * PLD + kpair], Vlo[(4 * cg + 2) * PLD + kpair]);
            bf_split2(va.w, vb.w, Vhi[(4 * cg + 3) * PLD + kpair], Vlo[(4 * cg + 3) * PLD + kpair]);
        }
        __syncthreads();

        // ---- S = Q @ K^T  (3xBF16, k16 per step) ----
        float sacc[8][4] = {};
        #pragma unroll
        for (int ks = 0; ks < 4; ks++) {
            const int ar = (qrow0 + lm) * PLD + ks * 8 + lk;
            uint32_t ah0 = Qhi[ar],           ah1 = Qhi[ar + 8 * PLD];
            uint32_t ah2 = Qhi[ar + 4],       ah3 = Qhi[ar + 8 * PLD + 4];
            uint32_t al0 = Qlo[ar],           al1 = Qlo[ar + 8 * PLD];
            uint32_t al2 = Qlo[ar + 4],       al3 = Qlo[ar + 8 * PLD + 4];
            #pragma unroll
            for (int ns = 0; ns < 8; ns++) {
                const int br = (ns * 8 + lm) * PLD + ks * 8 + lk;
                uint32_t bh0 = Khi[br], bh1 = Khi[br + 4];
                uint32_t bl0 = Klo[br], bl1 = Klo[br + 4];
                mma_bf16(sacc[ns], ah0, ah1, ah2, ah3, bh0, bh1);
                mma_bf16(sacc[ns], al0, al1, al2, al3, bh0, bh1);
                mma_bf16(sacc[ns], ah0, ah1, ah2, ah3, bl0, bl1);
            }
        }

        // ---- P = exp(8S - 8); split to bf16 pairs at store time ----
        #pragma unroll
        for (int ns = 0; ns < 8; ns++) {
            const float p0 = __expf(8.0f * sacc[ns][0] - 8.0f);
            const float p1 = __expf(8.0f * sacc[ns][1] - 8.0f);
            const float p2 = __expf(8.0f * sacc[ns][2] - 8.0f);
            const float p3 = __expf(8.0f * sacc[ns][3] - 8.0f);
            l0 += p0 + p1;
            l1 += p2 + p3;
            const int pr = ns * 4 + lk;             // key-pair index
            bf_split2(p0, p1, Phi[(qrow0 + lm) * PLD + pr],     Plo[(qrow0 + lm) * PLD + pr]);
            bf_split2(p2, p3, Phi[(qrow0 + 8 + lm) * PLD + pr], Plo[(qrow0 + 8 + lm) * PLD + pr]);
        }
        __syncwarp();   // P rows are warp-private

        // ---- O += P @ V  (3xBF16) ----
        #pragma unroll
        for (int ks = 0; ks < 4; ks++) {
            const int ar = (qrow0 + lm) * PLD + ks * 8 + lk;
            uint32_t ah0 = Phi[ar],           ah1 = Phi[ar + 8 * PLD];
            uint32_t ah2 = Phi[ar + 4],       ah3 = Phi[ar + 8 * PLD + 4];
            uint32_t al0 = Plo[ar],           al1 = Plo[ar + 8 * PLD];
            uint32_t al2 = Plo[ar + 4],       al3 = Plo[ar + 8 * PLD + 4];
            #pragma unroll
            for (int ns = 0; ns < 8; ns++) {
                const int br = (ns * 8 + lm) * PLD + ks * 8 + lk;
                uint32_t vh0 = Vhi[br], vh1 = Vhi[br + 4];
                uint32_t vl0 = Vlo[br], vl1 = Vlo[br + 4];
                mma_bf16(oacc[ns], ah0, ah1, ah2, ah3, vh0, vh1);
                mma_bf16(oacc[ns], al0, al1, al2, al3, vh0, vh1);
                mma_bf16(oacc[ns], ah0, ah1, ah2, ah3, vl0, vl1);
            }
        }
    }

    // ---- Epilogue: row sums across lane quad, normalize, store ----
    l0 += __shfl_xor_sync(0xffffffffu, l0, 1);
    l0 += __shfl_xor_sync(0xffffffffu, l0, 2);
    l1 += __shfl_xor_sync(0xffffffffu, l1, 1);
    l1 += __shfl_xor_sync(0xffffffffu, l1, 2);
    const float i0 = 1.0f / l0, i1 = 1.0f / l1;

    const int q0 = blockIdx.x * 128 + qrow0 + lm;
    float* o0 = outp + (((size_t)b * N_SEQ + q0) * NH + h) * HD;
    float* o1 = o0 + (size_t)8 * NH * HD;
    #pragma unroll
    for (int ns = 0; ns < 8; ns++) {
        const int c = ns * 8 + 2 * lk;
        float2 w0 = { oacc[ns][0] * i0, oacc[ns][1] * i0 };
        float2 w1 = { oacc[ns][2] * i1, oacc[ns][3] * i1 };
        *(float2*)&o0[c] = w0;
        *(float2*)&o1[c] = w1;
    }
}

// ---------------------------------------------------------------------------
extern "C" void kernel_launch(void* const* d_in, const int* in_sizes, int n_in,
                              void* d_out, int out_size)
{
    const float* x      = (const float*)d_in[0];
    const float* w_qkv  = (const float*)d_in[1];
    const float* b_qkv  = (const float*)d_in[2];
    const float* q_gain = (const float*)d_in[3];
    const float* k_gain = (const float*)d_in[4];
    const float* w_out  = (const float*)d_in[5];
    const float* b_out  = (const float*)d_in[6];
    float* out = (float*)d_out;

    float *qkv_p, *o_p;
    cudaGetSymbolAddress((void**)&qkv_p, g_qkv);
    cudaGetSymbolAddress((void**)&o_p, g_o);

    const int M = N_B * N_SEQ;  // 8192

    // 1) QKV projection (tf32 tensor cores, cp.async pipelined)
    sgemm_tf32<<<dim3((3 * DM) / 128, M / 128), 256>>>(x, w_qkv, b_qkv, qkv_p, M, 3 * DM, DM);

    // 2) RMSNorm + RoPE + L2-norm + head transpose
    prep_kernel<<<(N_B * N_SEQ * NH * 32) / 256, 256>>>(qkv_p, q_gain, k_gain);

    // 3) Tensor-core cosine-sim attention (3xBF16)
    cudaFuncSetAttribute(attn_tc, cudaFuncAttributeMaxDynamicSharedMemorySize,
                         (int)ATTN_SMEM_BYTES);
    attn_tc<<<dim3(N_SEQ / 128, NH, N_B), 256, ATTN_SMEM_BYTES>>>(o_p);

    // 4) Output projection (tf32 tensor cores, cp.async pipelined)
    sgemm_tf32<<<dim3(DM / 128, M / 128), 256>>>(o_p, w_out, b_out, out, M, DM, DM);
}

// round 13
// speedup vs baseline: 4.4308x; 1.0316x over previous
#include <cuda_runtime.h>
#include <cuda_bf16.h>
#include <math.h>
#include <stdint.h>

#define N_B   8
#define N_SEQ 1024
#define DM    1024
#define NH    16
#define HD    64

// Scratch (allocation-free: device globals)
__device__ float g_qkv[(size_t)N_B * N_SEQ * 3 * DM];
__device__ float g_q[(size_t)N_B * NH * N_SEQ * HD];
__device__ float g_k[(size_t)N_B * NH * N_SEQ * HD];
__device__ float g_v[(size_t)N_B * NH * N_SEQ * HD];
__device__ float g_o[(size_t)N_B * N_SEQ * DM];
// tf32-pre-rounded copies of GEMM operands
__device__ float g_xc[(size_t)N_B * N_SEQ * DM];
__device__ float g_wqc[(size_t)DM * 3 * DM];
__device__ float g_woc[(size_t)DM * DM];

// ---------------------------------------------------------------------------
// tf32 / bf16 / async helpers
// ---------------------------------------------------------------------------
__device__ __forceinline__ uint32_t f2tf32(float x) {
    uint32_t r;
    asm("cvt.rna.tf32.f32 %0, %1;" : "=r"(r) : "f"(x));
    return r;
}
__device__ __forceinline__ void mma_tf32(float c[4],
                                         uint32_t a0, uint32_t a1, uint32_t a2, uint32_t a3,
                                         uint32_t b0, uint32_t b1) {
    asm volatile(
        "mma.sync.aligned.m16n8k8.row.col.f32.tf32.tf32.f32 "
        "{%0,%1,%2,%3}, {%4,%5,%6,%7}, {%8,%9}, {%0,%1,%2,%3};\n"
        : "+f"(c[0]), "+f"(c[1]), "+f"(c[2]), "+f"(c[3])
        : "r"(a0), "r"(a1), "r"(a2), "r"(a3), "r"(b0), "r"(b1));
}
__device__ __forceinline__ void mma_bf16(float c[4],
                                         uint32_t a0, uint32_t a1, uint32_t a2, uint32_t a3,
                                         uint32_t b0, uint32_t b1) {
    asm volatile(
        "mma.sync.aligned.m16n8k16.row.col.f32.bf16.bf16.f32 "
        "{%0,%1,%2,%3}, {%4,%5,%6,%7}, {%8,%9}, {%0,%1,%2,%3};\n"
        : "+f"(c[0]), "+f"(c[1]), "+f"(c[2]), "+f"(c[3])
        : "r"(a0), "r"(a1), "r"(a2), "r"(a3), "r"(b0), "r"(b1));
}
__device__ __forceinline__ uint32_t bfpack(float x0, float x1) {
    uint32_t r;
    asm("cvt.rn.bf16x2.f32 %0, %1, %2;" : "=r"(r) : "f"(x1), "f"(x0));
    return r;
}
__device__ __forceinline__ void bf_split2(float x0, float x1, uint32_t& hi, uint32_t& lo) {
    hi = bfpack(x0, x1);
    __nv_bfloat162 h2 = *reinterpret_cast<__nv_bfloat162*>(&hi);
    lo = bfpack(x0 - __low2float(h2), x1 - __high2float(h2));
}
__device__ __forceinline__ void cp_async16(void* smem_dst, const void* gmem_src) {
    uint32_t s = (uint32_t)__cvta_generic_to_shared(smem_dst);
    asm volatile("cp.async.cg.shared.global [%0], [%1], 16;\n" :: "r"(s), "l"(gmem_src));
}
#define CP_COMMIT() asm volatile("cp.async.commit_group;\n" ::: "memory")
#define CP_WAIT(n)  asm volatile("cp.async.wait_group %0;\n" :: "n"(n) : "memory")

// ---------------------------------------------------------------------------
// Element-wise tf32 pre-rounding (hoists the GEMM's per-fragment cvt.rna)
// ---------------------------------------------------------------------------
__global__ __launch_bounds__(256)
void conv_tf32(const float* __restrict__ src, float* __restrict__ dst, int n4)
{
    const int i = blockIdx.x * blockDim.x + threadIdx.x;
    if (i < n4) {
        float4 v = ((const float4*)src)[i];
        uint4 u = { f2tf32(v.x), f2tf32(v.y), f2tf32(v.z), f2tf32(v.w) };
        ((uint4*)dst)[i] = u;
    }
}

// ---------------------------------------------------------------------------
// TF32 tensor-core GEMM v3: C = A@B + bias. Inputs MUST be tf32-pre-rounded.
// 128x128 tile, BK=16, 256 threads, warp tile 32x64.
// 3-stage cp.async pipeline; no cvt in mainloop (raw uint32 fragment loads).
// A smem [m][k] LDK=20 pad, B smem [k][n] LDB=136 pad (conflict-free).
// ---------------------------------------------------------------------------
#define LDK 20
#define LDB 136
#define ASZ (128 * LDK)
#define BSZ (16 * LDB)
#define STAGES 3

__global__ __launch_bounds__(256)
void sgemm_tf32(const float* __restrict__ A, const float* __restrict__ B,
                const float* __restrict__ bias, float* __restrict__ C,
                int M, int N, int K)
{
    __shared__ float As2[STAGES][ASZ];
    __shared__ float Bs2[STAGES][BSZ];

    const int tid  = threadIdx.x;
    const int lane = tid & 31;
    const int warp = tid >> 5;
    const int warpM = warp & 3;
    const int warpN = warp >> 2;
    const int lm = lane >> 2;
    const int lk = lane & 3;

    const int row0 = blockIdx.y * 128;
    const int col0 = blockIdx.x * 128;

    const int a_row0 = tid >> 2,  a_kc = (tid & 3) * 4;
    const int b_kr0  = tid >> 5,  b_nc = (tid & 31) * 4;

    float acc[2][8][4] = {};

    // tile loader: one committed group per tile
    auto load_tile = [&](int tile, int stage) {
        const int k0 = tile << 4;
        cp_async16(&As2[stage][a_row0 * LDK + a_kc],
                   A + (size_t)(row0 + a_row0) * K + k0 + a_kc);
        cp_async16(&As2[stage][(a_row0 + 64) * LDK + a_kc],
                   A + (size_t)(row0 + a_row0 + 64) * K + k0 + a_kc);
        cp_async16(&Bs2[stage][b_kr0 * LDB + b_nc],
                   B + (size_t)(k0 + b_kr0) * N + col0 + b_nc);
        cp_async16(&Bs2[stage][(b_kr0 + 8) * LDB + b_nc],
                   B + (size_t)(k0 + b_kr0 + 8) * N + col0 + b_nc);
        CP_COMMIT();
    };

    load_tile(0, 0);
    load_tile(1, 1);

    const int ntiles = K >> 4;
    for (int it = 0; it < ntiles; it++) {
        if (it + 1 < ntiles) { CP_WAIT(1); }   // tile `it` complete, next may fly
        else                 { CP_WAIT(0); }   // last tile: drain everything
        __syncthreads();

        const int buf = it % STAGES;
        const uint32_t* Asb = (const uint32_t*)As2[buf];
        const uint32_t* Bsb = (const uint32_t*)Bs2[buf];
        #pragma unroll
        for (int ks = 0; ks < 2; ks++) {
            uint32_t af[2][4];
            #pragma unroll
            for (int mm = 0; mm < 2; mm++) {
                const int mb = warpM * 32 + mm * 16 + lm;
                af[mm][0] = Asb[mb * LDK + ks * 8 + lk];
                af[mm][1] = Asb[(mb + 8) * LDK + ks * 8 + lk];
                af[mm][2] = Asb[mb * LDK + ks * 8 + lk + 4];
                af[mm][3] = Asb[(mb + 8) * LDK + ks * 8 + lk + 4];
            }
            uint32_t bf[8][2];
            #pragma unroll
            for (int nn = 0; nn < 8; nn++) {
                const int nb = warpN * 64 + nn * 8 + lm;
                bf[nn][0] = Bsb[(ks * 8 + lk) * LDB + nb];
                bf[nn][1] = Bsb[(ks * 8 + lk + 4) * LDB + nb];
            }
            #pragma unroll
            for (int mm = 0; mm < 2; mm++)
                #pragma unroll
                for (int nn = 0; nn < 8; nn++)
                    mma_tf32(acc[mm][nn], af[mm][0], af[mm][1], af[mm][2], af[mm][3],
                             bf[nn][0], bf[nn][1]);
        }
        // Refill the buffer we just freed (it-1's buffer was freed last iter;
        // (it+2)%STAGES == (it-1)%STAGES, all threads passed its compute before
        // this iteration's __syncthreads).
        if (it + 2 < ntiles) load_tile(it + 2, (it + 2) % STAGES);
    }

    #pragma unroll
    for (int mm = 0; mm < 2; mm++) {
        #pragma unroll
        for (int nn = 0; nn < 8; nn++) {
            const int r = row0 + warpM * 32 + mm * 16 + lm;
            const int c = col0 + warpN * 64 + nn * 8 + 2 * lk;
            float2 o0 = { acc[mm][nn][0] + bias[c], acc[mm][nn][1] + bias[c + 1] };
            float2 o1 = { acc[mm][nn][2] + bias[c], acc[mm][nn][3] + bias[c + 1] };
            *(float2*)&C[(size_t)r * N + c]       = o0;
            *(float2*)&C[(size_t)(r + 8) * N + c] = o1;
        }
    }
}

// ---------------------------------------------------------------------------
// Prep kernel (unchanged)
// ---------------------------------------------------------------------------
__global__ __launch_bounds__(256)
void prep_kernel(const float* __restrict__ qkv,
                 const float* __restrict__ q_gain,
                 const float* __restrict__ k_gain)
{
    const int w = (blockIdx.x * blockDim.x + threadIdx.x) >> 5;
    const int lane = threadIdx.x & 31;
    if (w >= N_B * N_SEQ * NH) return;
    const int h  = w % NH;
    const int bn = w / NH;
    const int n  = bn % N_SEQ;
    const int b  = bn / N_SEQ;

    const float* base = qkv + (size_t)bn * (3 * DM) + h * HD;
    float q0 = base[lane],          q1 = base[lane + 32];
    float k0 = base[DM + lane],     k1 = base[DM + lane + 32];
    float v0 = base[2 * DM + lane], v1 = base[2 * DM + lane + 32];

    const float pos = (lane < 16) ? (float)(n >> 5) : (float)(n & 31);
    const float fr = expf(-((float)(lane & 15) * (1.0f / 16.0f)) * 9.210340371976184f);
    float s, c;
    sincosf(pos * fr, &s, &c);

    const float gq0 = q_gain[lane], gq1 = q_gain[lane + 32];
    const float gk0 = k_gain[lane], gk1 = k_gain[lane + 32];

    float ssq = q0 * q0 + q1 * q1;
    #pragma unroll
    for (int o = 16; o; o >>= 1) ssq += __shfl_xor_sync(0xffffffffu, ssq, o);
    float r = rsqrtf(ssq * (1.0f / 64.0f) + 1e-6f);
    q0 *= r * gq0;  q1 *= r * gq1;
    float t0 = q0 * c - q1 * s;
    float t1 = q1 * c + q0 * s;
    float l2 = t0 * t0 + t1 * t1;
    #pragma unroll
    for (int o = 16; o; o >>= 1) l2 += __shfl_xor_sync(0xffffffffu, l2, o);
    float inv = rsqrtf(l2);
    t0 *= inv;  t1 *= inv;

    const size_t obase = (((size_t)(b * NH + h)) * N_SEQ + n) * HD;
    g_q[obase + lane] = t0;  g_q[obase + lane + 32] = t1;

    ssq = k0 * k0 + k1 * k1;
    #pragma unroll
    for (int o = 16; o; o >>= 1) ssq += __shfl_xor_sync(0xffffffffu, ssq, o);
    r = rsqrtf(ssq * (1.0f / 64.0f) + 1e-6f);
    k0 *= r * gk0;  k1 *= r * gk1;
    t0 = k0 * c - k1 * s;
    t1 = k1 * c + k0 * s;
    l2 = t0 * t0 + t1 * t1;
    #pragma unroll
    for (int o = 16; o; o >>= 1) l2 += __shfl_xor_sync(0xffffffffu, l2, o);
    inv = rsqrtf(l2);
    t0 *= inv;  t1 *= inv;
    g_k[obase + lane] = t0;  g_k[obase + lane + 32] = t1;

    g_v[obase + lane] = v0;  g_v[obase + lane + 32] = v1;
}

// ---------------------------------------------------------------------------
// Tensor-core cosine-sim flash attention, 3xBF16 (unchanged from R11 winner,
// except the epilogue pre-rounds output to tf32 for the out-projection GEMM).
// ---------------------------------------------------------------------------
#define PLD 36
#define ATTN_SMEM_BYTES ((size_t)(128*PLD*2 + 64*PLD*4 + 128*PLD*2) * 4)

__global__ __launch_bounds__(256, 2)
void attn_tc(float* __restrict__ outp)
{
    extern __shared__ uint32_t sm[];
    uint32_t* Qhi = sm;
    uint32_t* Qlo = Qhi + 128 * PLD;
    uint32_t* Khi = Qlo + 128 * PLD;
    uint32_t* Klo = Khi + 64 * PLD;
    uint32_t* Vhi = Klo + 64 * PLD;
    uint32_t* Vlo = Vhi + 64 * PLD;
    uint32_t* Phi = Vlo + 64 * PLD;
    uint32_t* Plo = Phi + 128 * PLD;

    const int h = blockIdx.y, b = blockIdx.z;
    const int t = threadIdx.x;
    const int lane = t & 31, warp = t >> 5;
    const int lm = lane >> 2, lk = lane & 3;
    const int qrow0 = warp * 16;
    const size_t bh = ((size_t)b * NH + h) * N_SEQ * HD;

    {
        const float4* qp = (const float4*)(g_q + bh + (size_t)blockIdx.x * 128 * HD);
        #pragma unroll
        for (int i = 0; i < 8; i++) {
            const int idx = t + i * 256;
            const int r = idx >> 4, pc = (idx & 15) * 2;
            float4 v = qp[idx];
            bf_split2(v.x, v.y, Qhi[r * PLD + pc],     Qlo[r * PLD + pc]);
            bf_split2(v.z, v.w, Qhi[r * PLD + pc + 1], Qlo[r * PLD + pc + 1]);
        }
    }

    float oacc[8][4] = {};
    float l0 = 0.0f, l1 = 0.0f;

    for (int kt = 0; kt < N_SEQ / 64; kt++) {
        __syncthreads();
        const float4* kp4 = (const float4*)(g_k + bh + (size_t)kt * 64 * HD);
        #pragma unroll
        for (int i = 0; i < 4; i++) {
            const int idx = t + i * 256;
            const int r = idx >> 4, pc = (idx & 15) * 2;
            float4 kv = kp4[idx];
            bf_split2(kv.x, kv.y, Khi[r * PLD + pc],     Klo[r * PLD + pc]);
            bf_split2(kv.z, kv.w, Khi[r * PLD + pc + 1], Klo[r * PLD + pc + 1]);
        }
        const float4* vp4 = (const float4*)(g_v + bh + (size_t)kt * 64 * HD);
        #pragma unroll
        for (int i = 0; i < 2; i++) {
            const int id = t + i * 256;
            const int kpair = id & 31, cg = id >> 5;
            float4 va = vp4[(2 * kpair) * 16 + cg];
            float4 vb = vp4[(2 * kpair + 1) * 16 + cg];
            bf_split2(va.x, vb.x, Vhi[(4 * cg + 0) * PLD + kpair], Vlo[(4 * cg + 0) * PLD + kpair]);
            bf_split2(va.y, vb.y, Vhi[(4 * cg + 1) * PLD + kpair], Vlo[(4 * cg + 1) * PLD + kpair]);
            bf_split2(va.z, vb.z, Vhi[(4 * cg + 2) * PLD + kpair], Vlo[(4 * cg + 2) * PLD + kpair]);
            bf_split2(va.w, vb.w, Vhi[(4 * cg + 3) * PLD + kpair], Vlo[(4 * cg + 3) * PLD + kpair]);
        }
        __syncthreads();

        float sacc[8][4] = {};
        #pragma unroll
        for (int ks = 0; ks < 4; ks++) {
            const int ar = (qrow0 + lm) * PLD + ks * 8 + lk;
            uint32_t ah0 = Qhi[ar],           ah1 = Qhi[ar + 8 * PLD];
            uint32_t ah2 = Qhi[ar + 4],       ah3 = Qhi[ar + 8 * PLD + 4];
            uint32_t al0 = Qlo[ar],           al1 = Qlo[ar + 8 * PLD];
            uint32_t al2 = Qlo[ar + 4],       al3 = Qlo[ar + 8 * PLD + 4];
            #pragma unroll
            for (int ns = 0; ns < 8; ns++) {
                const int br = (ns * 8 + lm) * PLD + ks * 8 + lk;
                uint32_t bh0 = Khi[br], bh1 = Khi[br + 4];
                uint32_t bl0 = Klo[br], bl1 = Klo[br + 4];
                mma_bf16(sacc[ns], ah0, ah1, ah2, ah3, bh0, bh1);
                mma_bf16(sacc[ns], al0, al1, al2, al3, bh0, bh1);
                mma_bf16(sacc[ns], ah0, ah1, ah2, ah3, bl0, bl1);
            }
        }

        #pragma unroll
        for (int ns = 0; ns < 8; ns++) {
            const float p0 = __expf(8.0f * sacc[ns][0] - 8.0f);
            const float p1 = __expf(8.0f * sacc[ns][1] - 8.0f);
            const float p2 = __expf(8.0f * sacc[ns][2] - 8.0f);
            const float p3 = __expf(8.0f * sacc[ns][3] - 8.0f);
            l0 += p0 + p1;
            l1 += p2 + p3;
            const int pr = ns * 4 + lk;
            bf_split2(p0, p1, Phi[(qrow0 + lm) * PLD + pr],     Plo[(qrow0 + lm) * PLD + pr]);
            bf_split2(p2, p3, Phi[(qrow0 + 8 + lm) * PLD + pr], Plo[(qrow0 + 8 + lm) * PLD + pr]);
        }
        __syncwarp();

        #pragma unroll
        for (int ks = 0; ks < 4; ks++) {
            const int ar = (qrow0 + lm) * PLD + ks * 8 + lk;
            uint32_t ah0 = Phi[ar],           ah1 = Phi[ar + 8 * PLD];
            uint32_t ah2 = Phi[ar + 4],       ah3 = Phi[ar + 8 * PLD + 4];
            uint32_t al0 = Plo[ar],           al1 = Plo[ar + 8 * PLD];
            uint32_t al2 = Plo[ar + 4],       al3 = Plo[ar + 8 * PLD + 4];
            #pragma unroll
            for (int ns = 0; ns < 8; ns++) {
                const int br = (ns * 8 + lm) * PLD + ks * 8 + lk;
                uint32_t vh0 = Vhi[br], vh1 = Vhi[br + 4];
                uint32_t vl0 = Vlo[br], vl1 = Vlo[br + 4];
                mma_bf16(oacc[ns], ah0, ah1, ah2, ah3, vh0, vh1);
                mma_bf16(oacc[ns], al0, al1, al2, al3, vh0, vh1);
                mma_bf16(oacc[ns], ah0, ah1, ah2, ah3, vl0, vl1);
            }
        }
    }

    l0 += __shfl_xor_sync(0xffffffffu, l0, 1);
    l0 += __shfl_xor_sync(0xffffffffu, l0, 2);
    l1 += __shfl_xor_sync(0xffffffffu, l1, 1);
    l1 += __shfl_xor_sync(0xffffffffu, l1, 2);
    const float i0 = 1.0f / l0, i1 = 1.0f / l1;

    const int q0 = blockIdx.x * 128 + qrow0 + lm;
    float* o0 = outp + (((size_t)b * N_SEQ + q0) * NH + h) * HD;
    float* o1 = o0 + (size_t)8 * NH * HD;
    // Pre-round to tf32 (rna) at store: identical arithmetic to the GEMM's
    // former per-fragment cvt, hoisted here so the GEMM mainloop is cvt-free.
    #pragma unroll
    for (int ns = 0; ns < 8; ns++) {
        const int c = ns * 8 + 2 * lk;
        float2 w0 = { __uint_as_float(f2tf32(oacc[ns][0] * i0)),
                      __uint_as_float(f2tf32(oacc[ns][1] * i0)) };
        float2 w1 = { __uint_as_float(f2tf32(oacc[ns][2] * i1)),
                      __uint_as_float(f2tf32(oacc[ns][3] * i1)) };
        *(float2*)&o0[c] = w0;
        *(float2*)&o1[c] = w1;
    }
}

// ---------------------------------------------------------------------------
extern "C" void kernel_launch(void* const* d_in, const int* in_sizes, int n_in,
                              void* d_out, int out_size)
{
    const float* x      = (const float*)d_in[0];
    const float* w_qkv  = (const float*)d_in[1];
    const float* b_qkv  = (const float*)d_in[2];
    const float* q_gain = (const float*)d_in[3];
    const float* k_gain = (const float*)d_in[4];
    const float* w_out  = (const float*)d_in[5];
    const float* b_out  = (const float*)d_in[6];
    float* out = (float*)d_out;

    float *qkv_p, *o_p, *xc_p, *wqc_p, *woc_p;
    cudaGetSymbolAddress((void**)&qkv_p, g_qkv);
    cudaGetSymbolAddress((void**)&o_p, g_o);
    cudaGetSymbolAddress((void**)&xc_p, g_xc);
    cudaGetSymbolAddress((void**)&wqc_p, g_wqc);
    cudaGetSymbolAddress((void**)&woc_p, g_woc);

    const int M = N_B * N_SEQ;  // 8192

    // 0) Pre-round GEMM operands to tf32 (hoisted cvt.rna)
    {
        const int nx  = (M * DM) / 4;
        const int nwq = (DM * 3 * DM) / 4;
        const int nwo = (DM * DM) / 4;
        conv_tf32<<<(nx  + 255) / 256, 256>>>(x,     xc_p,  nx);
        conv_tf32<<<(nwq + 255) / 256, 256>>>(w_qkv, wqc_p, nwq);
        conv_tf32<<<(nwo + 255) / 256, 256>>>(w_out, woc_p, nwo);
    }

    // 1) QKV projection (tf32 tensor cores, 3-stage cp.async, cvt-free loop)
    sgemm_tf32<<<dim3((3 * DM) / 128, M / 128), 256>>>(xc_p, wqc_p, b_qkv, qkv_p, M, 3 * DM, DM);

    // 2) RMSNorm + RoPE + L2-norm + head transpose
    prep_kernel<<<(N_B * N_SEQ * NH * 32) / 256, 256>>>(qkv_p, q_gain, k_gain);

    // 3) Tensor-core cosine-sim attention (3xBF16); writes tf32-rounded g_o
    cudaFuncSetAttribute(attn_tc, cudaFuncAttributeMaxDynamicSharedMemorySize,
                         (int)ATTN_SMEM_BYTES);
    attn_tc<<<dim3(N_SEQ / 128, NH, N_B), 256, ATTN_SMEM_BYTES>>>(o_p);

    // 4) Output projection (tf32 tensor cores)
    sgemm_tf32<<<dim3(DM / 128, M / 128), 256>>>(o_p, woc_p, b_out, out, M, DM, DM);
}

// round 16
// speedup vs baseline: 4.7267x; 1.0668x over previous
#include <cuda_runtime.h>
#include <cuda_bf16.h>
#include <math.h>
#include <stdint.h>

#define N_B   8
#define N_SEQ 1024
#define DM    1024
#define NH    16
#define HD    64

// Scratch (allocation-free: device globals)
__device__ float g_q[(size_t)N_B * NH * N_SEQ * HD];
__device__ float g_k[(size_t)N_B * NH * N_SEQ * HD];
__device__ float g_v[(size_t)N_B * NH * N_SEQ * HD];
__device__ float g_o[(size_t)N_B * N_SEQ * DM];
// tf32-pre-rounded copies of GEMM operands
__device__ float g_xc[(size_t)N_B * N_SEQ * DM];
__device__ float g_wqc[(size_t)DM * 3 * DM];
__device__ float g_woc[(size_t)DM * DM];
// RoPE tables: [n][j] for j = 0..31 (dims 32..63 reuse the same values)
__device__ float g_ropec[N_SEQ * 32];
__device__ float g_ropes[N_SEQ * 32];

// ---------------------------------------------------------------------------
// tf32 / bf16 / async helpers
// ---------------------------------------------------------------------------
__device__ __forceinline__ uint32_t f2tf32(float x) {
    uint32_t r;
    asm("cvt.rna.tf32.f32 %0, %1;" : "=r"(r) : "f"(x));
    return r;
}
__device__ __forceinline__ void mma_tf32(float c[4],
                                         uint32_t a0, uint32_t a1, uint32_t a2, uint32_t a3,
                                         uint32_t b0, uint32_t b1) {
    asm volatile(
        "mma.sync.aligned.m16n8k8.row.col.f32.tf32.tf32.f32 "
        "{%0,%1,%2,%3}, {%4,%5,%6,%7}, {%8,%9}, {%0,%1,%2,%3};\n"
        : "+f"(c[0]), "+f"(c[1]), "+f"(c[2]), "+f"(c[3])
        : "r"(a0), "r"(a1), "r"(a2), "r"(a3), "r"(b0), "r"(b1));
}
__device__ __forceinline__ void mma_bf16(float c[4],
                                         uint32_t a0, uint32_t a1, uint32_t a2, uint32_t a3,
                                         uint32_t b0, uint32_t b1) {
    asm volatile(
        "mma.sync.aligned.m16n8k16.row.col.f32.bf16.bf16.f32 "
        "{%0,%1,%2,%3}, {%4,%5,%6,%7}, {%8,%9}, {%0,%1,%2,%3};\n"
        : "+f"(c[0]), "+f"(c[1]), "+f"(c[2]), "+f"(c[3])
        : "r"(a0), "r"(a1), "r"(a2), "r"(a3), "r"(b0), "r"(b1));
}
__device__ __forceinline__ uint32_t bfpack(float x0, float x1) {
    uint32_t r;
    asm("cvt.rn.bf16x2.f32 %0, %1, %2;" : "=r"(r) : "f"(x1), "f"(x0));
    return r;
}
__device__ __forceinline__ void bf_split2(float x0, float x1, uint32_t& hi, uint32_t& lo) {
    hi = bfpack(x0, x1);
    __nv_bfloat162 h2 = *reinterpret_cast<__nv_bfloat162*>(&hi);
    lo = bfpack(x0 - __low2float(h2), x1 - __high2float(h2));
}
__device__ __forceinline__ void cp_async16(void* smem_dst, const void* gmem_src) {
    uint32_t s = (uint32_t)__cvta_generic_to_shared(smem_dst);
    asm volatile("cp.async.cg.shared.global [%0], [%1], 16;\n" :: "r"(s), "l"(gmem_src));
}
#define CP_COMMIT() asm volatile("cp.async.commit_group;\n" ::: "memory")
#define CP_WAIT(n)  asm volatile("cp.async.wait_group %0;\n" :: "n"(n) : "memory")

// ---------------------------------------------------------------------------
// Element-wise tf32 pre-rounding
// ---------------------------------------------------------------------------
__global__ __launch_bounds__(256)
void conv_tf32(const float* __restrict__ src, float* __restrict__ dst, int n4)
{
    const int i = blockIdx.x * blockDim.x + threadIdx.x;
    if (i < n4) {
        float4 v = ((const float4*)src)[i];
        uint4 u = { f2tf32(v.x), f2tf32(v.y), f2tf32(v.z), f2tf32(v.w) };
        ((uint4*)dst)[i] = u;
    }
}

// RoPE table init: identical angle math to the former prep kernel.
__global__ __launch_bounds__(256)
void rope_init()
{
    const int i = blockIdx.x * blockDim.x + threadIdx.x;   // 0..32767
    if (i >= N_SEQ * 32) return;
    const int n = i >> 5, j = i & 31;
    const float pos = (j < 16) ? (float)(n >> 5) : (float)(n & 31);
    const float fr = expf(-((float)(j & 15) * (1.0f / 16.0f)) * 9.210340371976184f);
    float s, c;
    sincosf(pos * fr, &s, &c);
    g_ropec[i] = c;
    g_ropes[i] = s;
}

// ---------------------------------------------------------------------------
// TF32 tensor-core GEMM: C = A@B + bias. Inputs tf32-pre-rounded.
// 128x128 tile, BK=16, 256 threads, warp tile 32x64, 3-stage cp.async.
// fuse=1: QKV epilogue — RMSNorm + RoPE + L2-norm per head, write g_q/g_k/g_v
// directly ([b,h,n,d] layout). fuse=0: plain bias epilogue to C.
// ---------------------------------------------------------------------------
#define LDK 20
#define LDB 136
#define ASZ (128 * LDK)
#define BSZ (16 * LDB)
#define STAGES 3

__global__ __launch_bounds__(256, 2)
void sgemm_tf32(const float* __restrict__ A, const float* __restrict__ B,
                const float* __restrict__ bias, float* __restrict__ C,
                int M, int N, int K,
                const float* __restrict__ qg, const float* __restrict__ kg, int fuse)
{
    __shared__ float As2[STAGES][ASZ];
    __shared__ float Bs2[STAGES][BSZ];

    const int tid  = threadIdx.x;
    const int lane = tid & 31;
    const int warp = tid >> 5;
    const int warpM = warp & 3;
    const int warpN = warp >> 2;
    const int lm = lane >> 2;
    const int lk = lane & 3;

    const int row0 = blockIdx.y * 128;
    const int col0 = blockIdx.x * 128;

    const int a_row0 = tid >> 2,  a_kc = (tid & 3) * 4;
    const int b_kr0  = tid >> 5,  b_nc = (tid & 31) * 4;

    float acc[2][8][4] = {};

    auto load_tile = [&](int tile, int stage) {
        const int k0 = tile << 4;
        cp_async16(&As2[stage][a_row0 * LDK + a_kc],
                   A + (size_t)(row0 + a_row0) * K + k0 + a_kc);
        cp_async16(&As2[stage][(a_row0 + 64) * LDK + a_kc],
                   A + (size_t)(row0 + a_row0 + 64) * K + k0 + a_kc);
        cp_async16(&Bs2[stage][b_kr0 * LDB + b_nc],
                   B + (size_t)(k0 + b_kr0) * N + col0 + b_nc);
        cp_async16(&Bs2[stage][(b_kr0 + 8) * LDB + b_nc],
                   B + (size_t)(k0 + b_kr0 + 8) * N + col0 + b_nc);
        CP_COMMIT();
    };

    load_tile(0, 0);
    load_tile(1, 1);

    const int ntiles = K >> 4;
    for (int it = 0; it < ntiles; it++) {
        if (it + 1 < ntiles) { CP_WAIT(1); }
        else                 { CP_WAIT(0); }
        __syncthreads();

        const int buf = it % STAGES;
        const uint32_t* Asb = (const uint32_t*)As2[buf];
        const uint32_t* Bsb = (const uint32_t*)Bs2[buf];
        #pragma unroll
        for (int ks = 0; ks < 2; ks++) {
            uint32_t af[2][4];
            #pragma unroll
            for (int mm = 0; mm < 2; mm++) {
                const int mb = warpM * 32 + mm * 16 + lm;
                af[mm][0] = Asb[mb * LDK + ks * 8 + lk];
                af[mm][1] = Asb[(mb + 8) * LDK + ks * 8 + lk];
                af[mm][2] = Asb[mb * LDK + ks * 8 + lk + 4];
                af[mm][3] = Asb[(mb + 8) * LDK + ks * 8 + lk + 4];
            }
            uint32_t bf[8][2];
            #pragma unroll
            for (int nn = 0; nn < 8; nn++) {
                const int nb = warpN * 64 + nn * 8 + lm;
                bf[nn][0] = Bsb[(ks * 8 + lk) * LDB + nb];
                bf[nn][1] = Bsb[(ks * 8 + lk + 4) * LDB + nb];
            }
            #pragma unroll
            for (int mm = 0; mm < 2; mm++)
                #pragma unroll
                for (int nn = 0; nn < 8; nn++)
                    mma_tf32(acc[mm][nn], af[mm][0], af[mm][1], af[mm][2], af[mm][3],
                             bf[nn][0], bf[nn][1]);
        }
        if (it + 2 < ntiles) load_tile(it + 2, (it + 2) % STAGES);
    }

    if (!fuse) {
        #pragma unroll
        for (int mm = 0; mm < 2; mm++) {
            #pragma unroll
            for (int nn = 0; nn < 8; nn++) {
                const int r = row0 + warpM * 32 + mm * 16 + lm;
                const int c = col0 + warpN * 64 + nn * 8 + 2 * lk;
                float2 o0 = { acc[mm][nn][0] + bias[c], acc[mm][nn][1] + bias[c + 1] };
                float2 o1 = { acc[mm][nn][2] + bias[c], acc[mm][nn][3] + bias[c + 1] };
                *(float2*)&C[(size_t)r * N + c]       = o0;
                *(float2*)&C[(size_t)(r + 8) * N + c] = o1;
            }
        }
        return;
    }

    // ---- Fused QKV epilogue ----
    // This warp's 64-col half-tile is one complete head of one section.
    const int cb  = col0 + warpN * 64;       // absolute N col (0..3071)
    const int sec = cb >> 10;                // 0=q, 1=k, 2=v (uniform per block)
    const int hh  = (cb & 1023) >> 6;        // head index
    const float* gains = (sec == 0) ? qg : kg;

    #pragma unroll
    for (int mm = 0; mm < 2; mm++) {
        #pragma unroll
        for (int p = 0; p < 2; p++) {
            const int r = row0 + warpM * 32 + mm * 16 + p * 8 + lm;  // token
            const int n = r & 1023;
            const size_t ob = (((size_t)((r >> 10) * NH + hh)) * N_SEQ + n) * HD;

            float v0[8], v1[8];
            #pragma unroll
            for (int nn = 0; nn < 8; nn++) {
                const int j = nn * 8 + 2 * lk;
                v0[nn] = acc[mm][nn][2 * p]     + bias[cb + j];
                v1[nn] = acc[mm][nn][2 * p + 1] + bias[cb + j + 1];
            }

            if (sec == 2) {                  // V: plain store
                float* dst = g_v + ob;
                #pragma unroll
                for (int nn = 0; nn < 8; nn++) {
                    float2 w = { v0[nn], v1[nn] };
                    *(float2*)&dst[nn * 8 + 2 * lk] = w;
                }
            } else {
                // RMSNorm over head dim (quad = same row, 16 cols each)
                float ss = 0.0f;
                #pragma unroll
                for (int nn = 0; nn < 8; nn++) ss += v0[nn] * v0[nn] + v1[nn] * v1[nn];
                ss += __shfl_xor_sync(0xffffffffu, ss, 1);
                ss += __shfl_xor_sync(0xffffffffu, ss, 2);
                const float rs = rsqrtf(ss * (1.0f / 64.0f) + 1e-6f);
                #pragma unroll
                for (int nn = 0; nn < 8; nn++) {
                    const int j = nn * 8 + 2 * lk;
                    v0[nn] *= rs * gains[j];
                    v1[nn] *= rs * gains[j + 1];
                }
                // RoPE: dims j (nn<4) pair with j+32 (nn+4), same thread
                #pragma unroll
                for (int nn = 0; nn < 4; nn++) {
                    const int j = nn * 8 + 2 * lk;
                    const float c0 = g_ropec[n * 32 + j],     s0 = g_ropes[n * 32 + j];
                    const float c1 = g_ropec[n * 32 + j + 1], s1 = g_ropes[n * 32 + j + 1];
                    const float a0 = v0[nn], b0 = v0[nn + 4];
                    v0[nn]     = a0 * c0 - b0 * s0;
                    v0[nn + 4] = b0 * c0 + a0 * s0;
                    const float a1 = v1[nn], b1 = v1[nn + 4];
                    v1[nn]     = a1 * c1 - b1 * s1;
                    v1[nn + 4] = b1 * c1 + a1 * s1;
                }
                // L2 normalize
                float l2 = 0.0f;
                #pragma unroll
                for (int nn = 0; nn < 8; nn++) l2 += v0[nn] * v0[nn] + v1[nn] * v1[nn];
                l2 += __shfl_xor_sync(0xffffffffu, l2, 1);
                l2 += __shfl_xor_sync(0xffffffffu, l2, 2);
                const float inv = rsqrtf(l2);
                float* dst = (sec == 0) ? (g_q + ob) : (g_k + ob);
                #pragma unroll
                for (int nn = 0; nn < 8; nn++) {
                    float2 w = { v0[nn] * inv, v1[nn] * inv };
                    *(float2*)&dst[nn * 8 + 2 * lk] = w;
                }
            }
        }
    }
}

// ---------------------------------------------------------------------------
// Tensor-core cosine-sim flash attention, 3xBF16 (R13 winner, unchanged)
// ---------------------------------------------------------------------------
#define PLD 36
#define ATTN_SMEM_BYTES ((size_t)(128*PLD*2 + 64*PLD*4 + 128*PLD*2) * 4)

__global__ __launch_bounds__(256, 2)
void attn_tc(float* __restrict__ outp)
{
    extern __shared__ uint32_t sm[];
    uint32_t* Qhi = sm;
    uint32_t* Qlo = Qhi + 128 * PLD;
    uint32_t* Khi = Qlo + 128 * PLD;
    uint32_t* Klo = Khi + 64 * PLD;
    uint32_t* Vhi = Klo + 64 * PLD;
    uint32_t* Vlo = Vhi + 64 * PLD;
    uint32_t* Phi = Vlo + 64 * PLD;
    uint32_t* Plo = Phi + 128 * PLD;

    const int h = blockIdx.y, b = blockIdx.z;
    const int t = threadIdx.x;
    const int lane = t & 31, warp = t >> 5;
    const int lm = lane >> 2, lk = lane & 3;
    const int qrow0 = warp * 16;
    const size_t bh = ((size_t)b * NH + h) * N_SEQ * HD;

    {
        const float4* qp = (const float4*)(g_q + bh + (size_t)blockIdx.x * 128 * HD);
        #pragma unroll
        for (int i = 0; i < 8; i++) {
            const int idx = t + i * 256;
            const int r = idx >> 4, pc = (idx & 15) * 2;
            float4 v = qp[idx];
            bf_split2(v.x, v.y, Qhi[r * PLD + pc],     Qlo[r * PLD + pc]);
            bf_split2(v.z, v.w, Qhi[r * PLD + pc + 1], Qlo[r * PLD + pc + 1]);
        }
    }

    float oacc[8][4] = {};
    float l0 = 0.0f, l1 = 0.0f;

    for (int kt = 0; kt < N_SEQ / 64; kt++) {
        __syncthreads();
        const float4* kp4 = (const float4*)(g_k + bh + (size_t)kt * 64 * HD);
        #pragma unroll
        for (int i = 0; i < 4; i++) {
            const int idx = t + i * 256;
            const int r = idx >> 4, pc = (idx & 15) * 2;
            float4 kv = kp4[idx];
            bf_split2(kv.x, kv.y, Khi[r * PLD + pc],     Klo[r * PLD + pc]);
            bf_split2(kv.z, kv.w, Khi[r * PLD + pc + 1], Klo[r * PLD + pc + 1]);
        }
        const float4* vp4 = (const float4*)(g_v + bh + (size_t)kt * 64 * HD);
        #pragma unroll
        for (int i = 0; i < 2; i++) {
            const int id = t + i * 256;
            const int kpair = id & 31, cg = id >> 5;
            float4 va = vp4[(2 * kpair) * 16 + cg];
            float4 vb = vp4[(2 * kpair + 1) * 16 + cg];
            bf_split2(va.x, vb.x, Vhi[(4 * cg + 0) * PLD + kpair], Vlo[(4 * cg + 0) * PLD + kpair]);
            bf_split2(va.y, vb.y, Vhi[(4 * cg + 1) * PLD + kpair], Vlo[(4 * cg + 1) * PLD + kpair]);
            bf_split2(va.z, vb.z, Vhi[(4 * cg + 2) * PLD + kpair], Vlo[(4 * cg + 2) * PLD + kpair]);
            bf_split2(va.w, vb.w, Vhi[(4 * cg + 3) * PLD + kpair], Vlo[(4 * cg + 3) * PLD + kpair]);
        }
        __syncthreads();

        float sacc[8][4] = {};
        #pragma unroll
        for (int ks = 0; ks < 4; ks++) {
            const int ar = (qrow0 + lm) * PLD + ks * 8 + lk;
            uint32_t ah0 = Qhi[ar],           ah1 = Qhi[ar + 8 * PLD];
            uint32_t ah2 = Qhi[ar + 4],       ah3 = Qhi[ar + 8 * PLD + 4];
            uint32_t al0 = Qlo[ar],           al1 = Qlo[ar + 8 * PLD];
            uint32_t al2 = Qlo[ar + 4],       al3 = Qlo[ar + 8 * PLD + 4];
            #pragma unroll
            for (int ns = 0; ns < 8; ns++) {
                const int br = (ns * 8 + lm) * PLD + ks * 8 + lk;
                uint32_t bh0 = Khi[br], bh1 = Khi[br + 4];
                uint32_t bl0 = Klo[br], bl1 = Klo[br + 4];
                mma_bf16(sacc[ns], ah0, ah1, ah2, ah3, bh0, bh1);
                mma_bf16(sacc[ns], al0, al1, al2, al3, bh0, bh1);
                mma_bf16(sacc[ns], ah0, ah1, ah2, ah3, bl0, bl1);
            }
        }

        #pragma unroll
        for (int ns = 0; ns < 8; ns++) {
            const float p0 = __expf(8.0f * sacc[ns][0] - 8.0f);
            const float p1 = __expf(8.0f * sacc[ns][1] - 8.0f);
            const float p2 = __expf(8.0f * sacc[ns][2] - 8.0f);
            const float p3 = __expf(8.0f * sacc[ns][3] - 8.0f);
            l0 += p0 + p1;
            l1 += p2 + p3;
            const int pr = ns * 4 + lk;
            bf_split2(p0, p1, Phi[(qrow0 + lm) * PLD + pr],     Plo[(qrow0 + lm) * PLD + pr]);
            bf_split2(p2, p3, Phi[(qrow0 + 8 + lm) * PLD + pr], Plo[(qrow0 + 8 + lm) * PLD + pr]);
        }
        __syncwarp();

        #pragma unroll
        for (int ks = 0; ks < 4; ks++) {
            const int ar = (qrow0 + lm) * PLD + ks * 8 + lk;
            uint32_t ah0 = Phi[ar],           ah1 = Phi[ar + 8 * PLD];
            uint32_t ah2 = Phi[ar + 4],       ah3 = Phi[ar + 8 * PLD + 4];
            uint32_t al0 = Plo[ar],           al1 = Plo[ar + 8 * PLD];
            uint32_t al2 = Plo[ar + 4],       al3 = Plo[ar + 8 * PLD + 4];
            #pragma unroll
            for (int ns = 0; ns < 8; ns++) {
                const int br = (ns * 8 + lm) * PLD + ks * 8 + lk;
                uint32_t vh0 = Vhi[br], vh1 = Vhi[br + 4];
                uint32_t vl0 = Vlo[br], vl1 = Vlo[br + 4];
                mma_bf16(oacc[ns], ah0, ah1, ah2, ah3, vh0, vh1);
                mma_bf16(oacc[ns], al0, al1, al2, al3, vh0, vh1);
                mma_bf16(oacc[ns], ah0, ah1, ah2, ah3, vl0, vl1);
            }
        }
    }

    l0 += __shfl_xor_sync(0xffffffffu, l0, 1);
    l0 += __shfl_xor_sync(0xffffffffu, l0, 2);
    l1 += __shfl_xor_sync(0xffffffffu, l1, 1);
    l1 += __shfl_xor_sync(0xffffffffu, l1, 2);
    const float i0 = 1.0f / l0, i1 = 1.0f / l1;

    const int q0 = blockIdx.x * 128 + qrow0 + lm;
    float* o0 = outp + (((size_t)b * N_SEQ + q0) * NH + h) * HD;
    float* o1 = o0 + (size_t)8 * NH * HD;
    #pragma unroll
    for (int ns = 0; ns < 8; ns++) {
        const int c = ns * 8 + 2 * lk;
        float2 w0 = { __uint_as_float(f2tf32(oacc[ns][0] * i0)),
                      __uint_as_float(f2tf32(oacc[ns][1] * i0)) };
        float2 w1 = { __uint_as_float(f2tf32(oacc[ns][2] * i1)),
                      __uint_as_float(f2tf32(oacc[ns][3] * i1)) };
        *(float2*)&o0[c] = w0;
        *(float2*)&o1[c] = w1;
    }
}

// ---------------------------------------------------------------------------
extern "C" void kernel_launch(void* const* d_in, const int* in_sizes, int n_in,
                              void* d_out, int out_size)
{
    const float* x      = (const float*)d_in[0];
    const float* w_qkv  = (const float*)d_in[1];
    const float* b_qkv  = (const float*)d_in[2];
    const float* q_gain = (const float*)d_in[3];
    const float* k_gain = (const float*)d_in[4];
    const float* w_out  = (const float*)d_in[5];
    const float* b_out  = (const float*)d_in[6];
    float* out = (float*)d_out;

    float *o_p, *xc_p, *wqc_p, *woc_p;
    cudaGetSymbolAddress((void**)&o_p, g_o);
    cudaGetSymbolAddress((void**)&xc_p, g_xc);
    cudaGetSymbolAddress((void**)&wqc_p, g_wqc);
    cudaGetSymbolAddress((void**)&woc_p, g_woc);

    const int M = N_B * N_SEQ;  // 8192

    // 0) Pre-round GEMM operands to tf32; build RoPE tables
    conv_tf32<<<(M * DM / 4 + 255) / 256, 256>>>(x, xc_p, M * DM / 4);
    conv_tf32<<<(DM * 3 * DM / 4 + 255) / 256, 256>>>(w_qkv, wqc_p, DM * 3 * DM / 4);
    conv_tf32<<<(DM * DM / 4 + 255) / 256, 256>>>(w_out, woc_p, DM * DM / 4);
    rope_init<<<(N_SEQ * 32 + 255) / 256, 256>>>();

    // 1) QKV projection with FUSED RMSNorm+RoPE+L2-norm epilogue -> g_q/g_k/g_v
    sgemm_tf32<<<dim3((3 * DM) / 128, M / 128), 256>>>(
        xc_p, wqc_p, b_qkv, nullptr, M, 3 * DM, DM, q_gain, k_gain, 1);

    // 2) Tensor-core cosine-sim attention (3xBF16); writes tf32-rounded g_o
    cudaFuncSetAttribute(attn_tc, cudaFuncAttributeMaxDynamicSharedMemorySize,
                         (int)ATTN_SMEM_BYTES);
    attn_tc<<<dim3(N_SEQ / 128, NH, N_B), 256, ATTN_SMEM_BYTES>>>(o_p);

    // 3) Output projection (plain epilogue)
    sgemm_tf32<<<dim3(DM / 128, M / 128), 256>>>(
        o_p, woc_p, b_out, out, M, DM, DM, nullptr, nullptr, 0);
}

// round 17
// speedup vs baseline: 4.8156x; 1.0188x over previous
#include <cuda_runtime.h>
#include <cuda_bf16.h>
#include <math.h>
#include <stdint.h>

#define N_B   8
#define N_SEQ 1024
#define DM    1024
#define NH    16
#define HD    64

// Scratch (allocation-free: device globals)
__device__ float g_q[(size_t)N_B * NH * N_SEQ * HD];
__device__ float g_k[(size_t)N_B * NH * N_SEQ * HD];
__device__ float g_v[(size_t)N_B * NH * N_SEQ * HD];
__device__ float g_o[(size_t)N_B * N_SEQ * DM];
// tf32-pre-rounded copies of GEMM operands
__device__ float g_xc[(size_t)N_B * N_SEQ * DM];
__device__ float g_wqc[(size_t)DM * 3 * DM];
__device__ float g_woc[(size_t)DM * DM];
// RoPE tables: [n][j] for j = 0..31 (dims 32..63 reuse the same values)
__device__ float g_ropec[N_SEQ * 32];
__device__ float g_ropes[N_SEQ * 32];

// ---------------------------------------------------------------------------
// tf32 / bf16 / async helpers
// ---------------------------------------------------------------------------
__device__ __forceinline__ uint32_t f2tf32(float x) {
    uint32_t r;
    asm("cvt.rna.tf32.f32 %0, %1;" : "=r"(r) : "f"(x));
    return r;
}
__device__ __forceinline__ void mma_tf32(float c[4],
                                         uint32_t a0, uint32_t a1, uint32_t a2, uint32_t a3,
                                         uint32_t b0, uint32_t b1) {
    asm volatile(
        "mma.sync.aligned.m16n8k8.row.col.f32.tf32.tf32.f32 "
        "{%0,%1,%2,%3}, {%4,%5,%6,%7}, {%8,%9}, {%0,%1,%2,%3};\n"
        : "+f"(c[0]), "+f"(c[1]), "+f"(c[2]), "+f"(c[3])
        : "r"(a0), "r"(a1), "r"(a2), "r"(a3), "r"(b0), "r"(b1));
}
__device__ __forceinline__ void mma_bf16(float c[4],
                                         uint32_t a0, uint32_t a1, uint32_t a2, uint32_t a3,
                                         uint32_t b0, uint32_t b1) {
    asm volatile(
        "mma.sync.aligned.m16n8k16.row.col.f32.bf16.bf16.f32 "
        "{%0,%1,%2,%3}, {%4,%5,%6,%7}, {%8,%9}, {%0,%1,%2,%3};\n"
        : "+f"(c[0]), "+f"(c[1]), "+f"(c[2]), "+f"(c[3])
        : "r"(a0), "r"(a1), "r"(a2), "r"(a3), "r"(b0), "r"(b1));
}
__device__ __forceinline__ uint32_t bfpack(float x0, float x1) {
    uint32_t r;
    asm("cvt.rn.bf16x2.f32 %0, %1, %2;" : "=r"(r) : "f"(x1), "f"(x0));
    return r;
}
__device__ __forceinline__ void bf_split2(float x0, float x1, uint32_t& hi, uint32_t& lo) {
    hi = bfpack(x0, x1);
    __nv_bfloat162 h2 = *reinterpret_cast<__nv_bfloat162*>(&hi);
    lo = bfpack(x0 - __low2float(h2), x1 - __high2float(h2));
}
__device__ __forceinline__ void cp_async16(void* smem_dst, const void* gmem_src) {
    uint32_t s = (uint32_t)__cvta_generic_to_shared(smem_dst);
    asm volatile("cp.async.cg.shared.global [%0], [%1], 16;\n" :: "r"(s), "l"(gmem_src));
}
#define CP_COMMIT() asm volatile("cp.async.commit_group;\n" ::: "memory")
#define CP_WAIT(n)  asm volatile("cp.async.wait_group %0;\n" :: "n"(n) : "memory")

// ---------------------------------------------------------------------------
// Element-wise tf32 pre-rounding
// ---------------------------------------------------------------------------
__global__ __launch_bounds__(256)
void conv_tf32(const float* __restrict__ src, float* __restrict__ dst, int n4)
{
    const int i = blockIdx.x * blockDim.x + threadIdx.x;
    if (i < n4) {
        float4 v = ((const float4*)src)[i];
        uint4 u = { f2tf32(v.x), f2tf32(v.y), f2tf32(v.z), f2tf32(v.w) };
        ((uint4*)dst)[i] = u;
    }
}

// RoPE table init: identical angle math to the original reference.
__global__ __launch_bounds__(256)
void rope_init()
{
    const int i = blockIdx.x * blockDim.x + threadIdx.x;   // 0..32767
    if (i >= N_SEQ * 32) return;
    const int n = i >> 5, j = i & 31;
    const float pos = (j < 16) ? (float)(n >> 5) : (float)(n & 31);
    const float fr = expf(-((float)(j & 15) * (1.0f / 16.0f)) * 9.210340371976184f);
    float s, c;
    sincosf(pos * fr, &s, &c);
    g_ropec[i] = c;
    g_ropes[i] = s;
}

// ---------------------------------------------------------------------------
// TF32 tensor-core GEMM (R16 winner, unchanged): C = A@B + bias.
// fuse=1: QKV epilogue (RMSNorm + RoPE + L2-norm) -> g_q/g_k/g_v.
// ---------------------------------------------------------------------------
#define LDK 20
#define LDB 136
#define ASZ (128 * LDK)
#define BSZ (16 * LDB)
#define STAGES 3

__global__ __launch_bounds__(256, 2)
void sgemm_tf32(const float* __restrict__ A, const float* __restrict__ B,
                const float* __restrict__ bias, float* __restrict__ C,
                int M, int N, int K,
                const float* __restrict__ qg, const float* __restrict__ kg, int fuse)
{
    __shared__ float As2[STAGES][ASZ];
    __shared__ float Bs2[STAGES][BSZ];

    const int tid  = threadIdx.x;
    const int lane = tid & 31;
    const int warp = tid >> 5;
    const int warpM = warp & 3;
    const int warpN = warp >> 2;
    const int lm = lane >> 2;
    const int lk = lane & 3;

    const int row0 = blockIdx.y * 128;
    const int col0 = blockIdx.x * 128;

    const int a_row0 = tid >> 2,  a_kc = (tid & 3) * 4;
    const int b_kr0  = tid >> 5,  b_nc = (tid & 31) * 4;

    float acc[2][8][4] = {};

    auto load_tile = [&](int tile, int stage) {
        const int k0 = tile << 4;
        cp_async16(&As2[stage][a_row0 * LDK + a_kc],
                   A + (size_t)(row0 + a_row0) * K + k0 + a_kc);
        cp_async16(&As2[stage][(a_row0 + 64) * LDK + a_kc],
                   A + (size_t)(row0 + a_row0 + 64) * K + k0 + a_kc);
        cp_async16(&Bs2[stage][b_kr0 * LDB + b_nc],
                   B + (size_t)(k0 + b_kr0) * N + col0 + b_nc);
        cp_async16(&Bs2[stage][(b_kr0 + 8) * LDB + b_nc],
                   B + (size_t)(k0 + b_kr0 + 8) * N + col0 + b_nc);
        CP_COMMIT();
    };

    load_tile(0, 0);
    load_tile(1, 1);

    const int ntiles = K >> 4;
    for (int it = 0; it < ntiles; it++) {
        if (it + 1 < ntiles) { CP_WAIT(1); }
        else                 { CP_WAIT(0); }
        __syncthreads();

        const int buf = it % STAGES;
        const uint32_t* Asb = (const uint32_t*)As2[buf];
        const uint32_t* Bsb = (const uint32_t*)Bs2[buf];
        #pragma unroll
        for (int ks = 0; ks < 2; ks++) {
            uint32_t af[2][4];
            #pragma unroll
            for (int mm = 0; mm < 2; mm++) {
                const int mb = warpM * 32 + mm * 16 + lm;
                af[mm][0] = Asb[mb * LDK + ks * 8 + lk];
                af[mm][1] = Asb[(mb + 8) * LDK + ks * 8 + lk];
                af[mm][2] = Asb[mb * LDK + ks * 8 + lk + 4];
                af[mm][3] = Asb[(mb + 8) * LDK + ks * 8 + lk + 4];
            }
            uint32_t bf[8][2];
            #pragma unroll
            for (int nn = 0; nn < 8; nn++) {
                const int nb = warpN * 64 + nn * 8 + lm;
                bf[nn][0] = Bsb[(ks * 8 + lk) * LDB + nb];
                bf[nn][1] = Bsb[(ks * 8 + lk + 4) * LDB + nb];
            }
            #pragma unroll
            for (int mm = 0; mm < 2; mm++)
                #pragma unroll
                for (int nn = 0; nn < 8; nn++)
                    mma_tf32(acc[mm][nn], af[mm][0], af[mm][1], af[mm][2], af[mm][3],
                             bf[nn][0], bf[nn][1]);
        }
        if (it + 2 < ntiles) load_tile(it + 2, (it + 2) % STAGES);
    }

    if (!fuse) {
        #pragma unroll
        for (int mm = 0; mm < 2; mm++) {
            #pragma unroll
            for (int nn = 0; nn < 8; nn++) {
                const int r = row0 + warpM * 32 + mm * 16 + lm;
                const int c = col0 + warpN * 64 + nn * 8 + 2 * lk;
                float2 o0 = { acc[mm][nn][0] + bias[c], acc[mm][nn][1] + bias[c + 1] };
                float2 o1 = { acc[mm][nn][2] + bias[c], acc[mm][nn][3] + bias[c + 1] };
                *(float2*)&C[(size_t)r * N + c]       = o0;
                *(float2*)&C[(size_t)(r + 8) * N + c] = o1;
            }
        }
        return;
    }

    // ---- Fused QKV epilogue ----
    const int cb  = col0 + warpN * 64;
    const int sec = cb >> 10;                // 0=q, 1=k, 2=v
    const int hh  = (cb & 1023) >> 6;
    const float* gains = (sec == 0) ? qg : kg;

    #pragma unroll
    for (int mm = 0; mm < 2; mm++) {
        #pragma unroll
        for (int p = 0; p < 2; p++) {
            const int r = row0 + warpM * 32 + mm * 16 + p * 8 + lm;
            const int n = r & 1023;
            const size_t ob = (((size_t)((r >> 10) * NH + hh)) * N_SEQ + n) * HD;

            float v0[8], v1[8];
            #pragma unroll
            for (int nn = 0; nn < 8; nn++) {
                const int j = nn * 8 + 2 * lk;
                v0[nn] = acc[mm][nn][2 * p]     + bias[cb + j];
                v1[nn] = acc[mm][nn][2 * p + 1] + bias[cb + j + 1];
            }

            if (sec == 2) {
                float* dst = g_v + ob;
                #pragma unroll
                for (int nn = 0; nn < 8; nn++) {
                    float2 w = { v0[nn], v1[nn] };
                    *(float2*)&dst[nn * 8 + 2 * lk] = w;
                }
            } else {
                float ss = 0.0f;
                #pragma unroll
                for (int nn = 0; nn < 8; nn++) ss += v0[nn] * v0[nn] + v1[nn] * v1[nn];
                ss += __shfl_xor_sync(0xffffffffu, ss, 1);
                ss += __shfl_xor_sync(0xffffffffu, ss, 2);
                const float rs = rsqrtf(ss * (1.0f / 64.0f) + 1e-6f);
                #pragma unroll
                for (int nn = 0; nn < 8; nn++) {
                    const int j = nn * 8 + 2 * lk;
                    v0[nn] *= rs * gains[j];
                    v1[nn] *= rs * gains[j + 1];
                }
                #pragma unroll
                for (int nn = 0; nn < 4; nn++) {
                    const int j = nn * 8 + 2 * lk;
                    const float c0 = g_ropec[n * 32 + j],     s0 = g_ropes[n * 32 + j];
                    const float c1 = g_ropec[n * 32 + j + 1], s1 = g_ropes[n * 32 + j + 1];
                    const float a0 = v0[nn], b0 = v0[nn + 4];
                    v0[nn]     = a0 * c0 - b0 * s0;
                    v0[nn + 4] = b0 * c0 + a0 * s0;
                    const float a1 = v1[nn], b1 = v1[nn + 4];
                    v1[nn]     = a1 * c1 - b1 * s1;
                    v1[nn + 4] = b1 * c1 + a1 * s1;
                }
                float l2 = 0.0f;
                #pragma unroll
                for (int nn = 0; nn < 8; nn++) l2 += v0[nn] * v0[nn] + v1[nn] * v1[nn];
                l2 += __shfl_xor_sync(0xffffffffu, l2, 1);
                l2 += __shfl_xor_sync(0xffffffffu, l2, 2);
                const float inv = rsqrtf(l2);
                float* dst = (sec == 0) ? (g_q + ob) : (g_k + ob);
                #pragma unroll
                for (int nn = 0; nn < 8; nn++) {
                    float2 w = { v0[nn] * inv, v1[nn] * inv };
                    *(float2*)&dst[nn * 8 + 2 * lk] = w;
                }
            }
        }
    }
}

// ---------------------------------------------------------------------------
// Tensor-core cosine-sim flash attention, 3xBF16.
// v2: Q fragments hoisted to registers (loop-invariant); P routed
// C-frag -> registers -> A-frag directly (the m16n8k16 C layout of S IS the
// A layout for PV: a0,a1 = sacc[2ks] c0c1,c2c3; a2,a3 = sacc[2ks+1]).
// No P smem, no Q smem: static 36.9 KB (K/V planes only).
// ---------------------------------------------------------------------------
#define PLD 36

__global__ __launch_bounds__(256, 2)
void attn_tc(float* __restrict__ outp)
{
    __shared__ uint32_t Khi[64 * PLD], Klo[64 * PLD];
    __shared__ uint32_t Vhi[64 * PLD], Vlo[64 * PLD];

    const int h = blockIdx.y, b = blockIdx.z;
    const int t = threadIdx.x;
    const int lane = t & 31, warp = t >> 5;
    const int lm = lane >> 2, lk = lane & 3;
    const int qrow0 = warp * 16;
    const size_t bh = ((size_t)b * NH + h) * N_SEQ * HD;

    // ---- Q fragments: load once, gmem -> registers, hi/lo split ----
    uint32_t qh[4][4], ql[4][4];
    {
        const float* q0 = g_q + bh + (size_t)(blockIdx.x * 128 + qrow0 + lm) * HD;
        const float* q1 = q0 + 8 * HD;
        #pragma unroll
        for (int ks = 0; ks < 4; ks++) {
            const int kk = ks * 16 + 2 * lk;
            float2 a0 = *(const float2*)(q0 + kk);
            float2 a1 = *(const float2*)(q1 + kk);
            float2 a2 = *(const float2*)(q0 + kk + 8);
            float2 a3 = *(const float2*)(q1 + kk + 8);
            bf_split2(a0.x, a0.y, qh[ks][0], ql[ks][0]);
            bf_split2(a1.x, a1.y, qh[ks][1], ql[ks][1]);
            bf_split2(a2.x, a2.y, qh[ks][2], ql[ks][2]);
            bf_split2(a3.x, a3.y, qh[ks][3], ql[ks][3]);
        }
    }

    float oacc[8][4] = {};
    float l0 = 0.0f, l1 = 0.0f;

    for (int kt = 0; kt < N_SEQ / 64; kt++) {
        __syncthreads();
        // ---- K tile [64 keys x 64 d] -> hi/lo pairs along d ----
        const float4* kp4 = (const float4*)(g_k + bh + (size_t)kt * 64 * HD);
        #pragma unroll
        for (int i = 0; i < 4; i++) {
            const int idx = t + i * 256;
            const int r = idx >> 4, pc = (idx & 15) * 2;
            float4 kv = kp4[idx];
            bf_split2(kv.x, kv.y, Khi[r * PLD + pc],     Klo[r * PLD + pc]);
            bf_split2(kv.z, kv.w, Khi[r * PLD + pc + 1], Klo[r * PLD + pc + 1]);
        }
        // ---- V tile -> transposed [d][key-pair] hi/lo ----
        const float4* vp4 = (const float4*)(g_v + bh + (size_t)kt * 64 * HD);
        #pragma unroll
        for (int i = 0; i < 2; i++) {
            const int id = t + i * 256;
            const int kpair = id & 31, cg = id >> 5;
            float4 va = vp4[(2 * kpair) * 16 + cg];
            float4 vb = vp4[(2 * kpair + 1) * 16 + cg];
            bf_split2(va.x, vb.x, Vhi[(4 * cg + 0) * PLD + kpair], Vlo[(4 * cg + 0) * PLD + kpair]);
            bf_split2(va.y, vb.y, Vhi[(4 * cg + 1) * PLD + kpair], Vlo[(4 * cg + 1) * PLD + kpair]);
            bf_split2(va.z, vb.z, Vhi[(4 * cg + 2) * PLD + kpair], Vlo[(4 * cg + 2) * PLD + kpair]);
            bf_split2(va.w, vb.w, Vhi[(4 * cg + 3) * PLD + kpair], Vlo[(4 * cg + 3) * PLD + kpair]);
        }
        __syncthreads();

        // ---- S = Q @ K^T  (3xBF16, Q from registers) ----
        float sacc[8][4] = {};
        #pragma unroll
        for (int ks = 0; ks < 4; ks++) {
            #pragma unroll
            for (int ns = 0; ns < 8; ns++) {
                const int br = (ns * 8 + lm) * PLD + ks * 8 + lk;
                uint32_t bh0 = Khi[br], bh1 = Khi[br + 4];
                uint32_t bl0 = Klo[br], bl1 = Klo[br + 4];
                mma_bf16(sacc[ns], qh[ks][0], qh[ks][1], qh[ks][2], qh[ks][3], bh0, bh1);
                mma_bf16(sacc[ns], ql[ks][0], ql[ks][1], ql[ks][2], ql[ks][3], bh0, bh1);
                mma_bf16(sacc[ns], qh[ks][0], qh[ks][1], qh[ks][2], qh[ks][3], bl0, bl1);
            }
        }

        // ---- P = exp(8S - 8): C-frag -> A-frag entirely in registers ----
        uint32_t ph01[8], ph23[8], pl01[8], pl23[8];
        #pragma unroll
        for (int ns = 0; ns < 8; ns++) {
            const float p0 = __expf(8.0f * sacc[ns][0] - 8.0f);
            const float p1 = __expf(8.0f * sacc[ns][1] - 8.0f);
            const float p2 = __expf(8.0f * sacc[ns][2] - 8.0f);
            const float p3 = __expf(8.0f * sacc[ns][3] - 8.0f);
            l0 += p0 + p1;
            l1 += p2 + p3;
            bf_split2(p0, p1, ph01[ns], pl01[ns]);
            bf_split2(p2, p3, ph23[ns], pl23[ns]);
        }

        // ---- O += P @ V  (3xBF16, P A-frags from registers) ----
        #pragma unroll
        for (int ks = 0; ks < 4; ks++) {
            const uint32_t ah0 = ph01[2 * ks],     ah1 = ph23[2 * ks];
            const uint32_t ah2 = ph01[2 * ks + 1], ah3 = ph23[2 * ks + 1];
            const uint32_t al0 = pl01[2 * ks],     al1 = pl23[2 * ks];
            const uint32_t al2 = pl01[2 * ks + 1], al3 = pl23[2 * ks + 1];
            #pragma unroll
            for (int ns = 0; ns < 8; ns++) {
                const int br = (ns * 8 + lm) * PLD + ks * 8 + lk;
                uint32_t vh0 = Vhi[br], vh1 = Vhi[br + 4];
                uint32_t vl0 = Vlo[br], vl1 = Vlo[br + 4];
                mma_bf16(oacc[ns], ah0, ah1, ah2, ah3, vh0, vh1);
                mma_bf16(oacc[ns], al0, al1, al2, al3, vh0, vh1);
                mma_bf16(oacc[ns], ah0, ah1, ah2, ah3, vl0, vl1);
            }
        }
    }

    l0 += __shfl_xor_sync(0xffffffffu, l0, 1);
    l0 += __shfl_xor_sync(0xffffffffu, l0, 2);
    l1 += __shfl_xor_sync(0xffffffffu, l1, 1);
    l1 += __shfl_xor_sync(0xffffffffu, l1, 2);
    const float i0 = 1.0f / l0, i1 = 1.0f / l1;

    const int q0 = blockIdx.x * 128 + qrow0 + lm;
    float* o0 = outp + (((size_t)b * N_SEQ + q0) * NH + h) * HD;
    float* o1 = o0 + (size_t)8 * NH * HD;
    #pragma unroll
    for (int ns = 0; ns < 8; ns++) {
        const int c = ns * 8 + 2 * lk;
        float2 w0 = { __uint_as_float(f2tf32(oacc[ns][0] * i0)),
                      __uint_as_float(f2tf32(oacc[ns][1] * i0)) };
        float2 w1 = { __uint_as_float(f2tf32(oacc[ns][2] * i1)),
                      __uint_as_float(f2tf32(oacc[ns][3] * i1)) };
        *(float2*)&o0[c] = w0;
        *(float2*)&o1[c] = w1;
    }
}

// ---------------------------------------------------------------------------
extern "C" void kernel_launch(void* const* d_in, const int* in_sizes, int n_in,
                              void* d_out, int out_size)
{
    const float* x      = (const float*)d_in[0];
    const float* w_qkv  = (const float*)d_in[1];
    const float* b_qkv  = (const float*)d_in[2];
    const float* q_gain = (const float*)d_in[3];
    const float* k_gain = (const float*)d_in[4];
    const float* w_out  = (const float*)d_in[5];
    const float* b_out  = (const float*)d_in[6];
    float* out = (float*)d_out;

    float *o_p, *xc_p, *wqc_p, *woc_p;
    cudaGetSymbolAddress((void**)&o_p, g_o);
    cudaGetSymbolAddress((void**)&xc_p, g_xc);
    cudaGetSymbolAddress((void**)&wqc_p, g_wqc);
    cudaGetSymbolAddress((void**)&woc_p, g_woc);

    const int M = N_B * N_SEQ;  // 8192

    // 0) Pre-round GEMM operands to tf32; build RoPE tables
    conv_tf32<<<(M * DM / 4 + 255) / 256, 256>>>(x, xc_p, M * DM / 4);
    conv_tf32<<<(DM * 3 * DM / 4 + 255) / 256, 256>>>(w_qkv, wqc_p, DM * 3 * DM / 4);
    conv_tf32<<<(DM * DM / 4 + 255) / 256, 256>>>(w_out, woc_p, DM * DM / 4);
    rope_init<<<(N_SEQ * 32 + 255) / 256, 256>>>();

    // 1) QKV projection with fused RMSNorm+RoPE+L2-norm epilogue
    sgemm_tf32<<<dim3((3 * DM) / 128, M / 128), 256>>>(
        xc_p, wqc_p, b_qkv, nullptr, M, 3 * DM, DM, q_gain, k_gain, 1);

    // 2) Tensor-core cosine-sim attention (3xBF16, register-routed P)
    attn_tc<<<dim3(N_SEQ / 128, NH, N_B), 256>>>(o_p);

    // 3) Output projection
    sgemm_tf32<<<dim3(DM / 128, M / 128), 256>>>(
        o_p, woc_p, b_out, out, M, DM, DM, nullptr, nullptr, 0);
}